// round 5
// baseline (speedup 1.0000x reference)
#include <cuda_runtime.h>
#include <cuda_fp16.h>
#include <cstdint>

// ---------------------------------------------------------------------------
// FastAttention — linear attention with ReLU feature maps.
// Big GEMMs: fp16 mma.sync m16n8k16, CTA tile 128x256, warp tile 64x64.
// PHIV intermediate stored fp16. Accumulation everywhere fp32.
//
//   K1 build_weff : fold per-head orth proj into Wq/Wk -> g_WBIGH (fp16)
//   K2 copy_wv    : append Wv rows (fp16)
//   R1 round      : query -> g_XH (fp16)
//   R2 round      : Wo -> g_WORH (fp16)
//   G1 gemm_mma   : PHIVH[16384,3072](fp16) = XH @ WBIGH^T, relu cols [0,2048)
//   K4 kv_kernel  : split-K partial kv[64x64] + ksum[64] per (b,h)
//   K5 kv_reduce  : deterministic reduction
//   K6 attn_kernel: attn = inv * phiQ @ kv -> g_ATTNH (fp16)
//   G2 gemm_mma   : out(fp32) = ATTNH @ WORH^T + bo
// ---------------------------------------------------------------------------

// ------------------------- device scratch (no allocs) ----------------------
__device__ __align__(16) __half g_XH[(size_t)16384 * 1024];
__device__ __align__(16) __half g_WBIGH[(size_t)3072 * 1024];
__device__ __align__(16) __half g_WORH[(size_t)1024 * 1024];
__device__ __align__(16) __half g_ATTNH[(size_t)16384 * 1024];
__device__ __align__(16) __half g_PHIVH[(size_t)16384 * 3072];
__device__ float g_KV[64 * 64 * 64];
__device__ float g_KSUM[64 * 64];
__device__ float g_KVP[8 * 64 * 64 * 64];
__device__ float g_KSP[8 * 64 * 64];

// ------------------------- helpers ------------------------------------------
__device__ __forceinline__ uint32_t smem_u32(const void* p) {
    uint32_t a;
    asm("{ .reg .u64 t; cvta.to.shared.u64 t, %1; cvt.u32.u64 %0, t; }"
        : "=r"(a) : "l"(p));
    return a;
}
__device__ __forceinline__ void cp16(uint32_t dst, const void* src) {
    asm volatile("cp.async.cg.shared.global [%0], [%1], 16;" :: "r"(dst), "l"(src));
}
__device__ __forceinline__ void ldsm_x4(uint32_t& r0, uint32_t& r1,
                                        uint32_t& r2, uint32_t& r3, uint32_t a) {
    asm volatile("ldmatrix.sync.aligned.m8n8.x4.shared.b16 {%0,%1,%2,%3}, [%4];"
                 : "=r"(r0), "=r"(r1), "=r"(r2), "=r"(r3) : "r"(a));
}
__device__ __forceinline__ void mma_f16(float* c, uint32_t a0, uint32_t a1,
                                        uint32_t a2, uint32_t a3,
                                        uint32_t b0, uint32_t b1) {
    asm volatile(
        "mma.sync.aligned.m16n8k16.row.col.f32.f16.f16.f32 "
        "{%0,%1,%2,%3}, {%4,%5,%6,%7}, {%8,%9}, {%0,%1,%2,%3};"
        : "+f"(c[0]), "+f"(c[1]), "+f"(c[2]), "+f"(c[3])
        : "r"(a0), "r"(a1), "r"(a2), "r"(a3), "r"(b0), "r"(b1));
}

// ------------------------- K1: fused per-head weights (fp16 out) ------------
__global__ __launch_bounds__(256)
void build_weff_kernel(const float* __restrict__ Wq,
                       const float* __restrict__ Wk,
                       const float* __restrict__ P)
{
    int bid   = blockIdx.x;
    int which = bid >> 8;
    int rem   = bid & 255;
    int h     = rem >> 4;
    int chunk = rem & 15;
    const float* W = which ? Wk : Wq;

    __shared__ float Psh[64][64];
    __shared__ float Wsh[64][64];
    int tid = threadIdx.x;

#pragma unroll
    for (int i = 0; i < 4; i++) {
        int f = tid + i * 256;
        int e = f >> 4, c4 = (f & 15) << 2;
        *(float4*)&Psh[e][c4] = *(const float4*)(P + (size_t)h * 4096 + f * 4);
        *(float4*)&Wsh[e][c4] =
            *(const float4*)(W + (size_t)(h * 64 + e) * 1024 + chunk * 64 + c4);
    }
    __syncthreads();

    int dp = tid & 63;
    int dg = tid >> 6;
    float acc[16];
#pragma unroll
    for (int j = 0; j < 16; j++) acc[j] = 0.f;
#pragma unroll 4
    for (int e = 0; e < 64; e++) {
        float p = Psh[e][dp];
#pragma unroll
        for (int j = 0; j < 16; j++)
            acc[j] += p * Wsh[e][dg * 16 + j];
    }
    __half* dst = g_WBIGH + (size_t)(which * 1024 + h * 64 + dp) * 1024
                          + chunk * 64 + dg * 16;
#pragma unroll
    for (int j = 0; j < 16; j += 2)
        *(half2*)(dst + j) = __floats2half2_rn(acc[j], acc[j + 1]);
}

// ------------------------- K2: copy Wv (fp16) --------------------------------
__global__ __launch_bounds__(256)
void copy_wv_kernel(const float* __restrict__ Wv)
{
    int row = blockIdx.x;
    int tid = threadIdx.x;
    float4 v = *(const float4*)(Wv + (size_t)row * 1024 + tid * 4);
    __half* dst = g_WBIGH + (size_t)(2048 + row) * 1024 + tid * 4;
    *(half2*)(dst)     = __floats2half2_rn(v.x, v.y);
    *(half2*)(dst + 2) = __floats2half2_rn(v.z, v.w);
}

// ------------------------- round fp32 -> fp16 --------------------------------
__global__ __launch_bounds__(256)
void round_half_kernel(const float* __restrict__ src, __half* __restrict__ dst)
{
    size_t i = ((size_t)blockIdx.x * 256 + threadIdx.x) * 4;
    float4 v = *(const float4*)(src + i);
    *(half2*)(dst + i)     = __floats2half2_rn(v.x, v.y);
    *(half2*)(dst + i + 2) = __floats2half2_rn(v.z, v.w);
}

// ------------------------- fp16 mma GEMM ------------------------------------
// C[M,N] = A[M,K] @ B[N,K]^T (+bias, +relu on cols < relu_cols)
// CTA tile 128x256x32, 256 threads (8 warps 2x4), warp tile 64x64.
// 3-stage cp.async ring; SMEM rows 32 halfs + pad -> 80B stride.
constexpr int HROW_B    = 80;
constexpr int A_TILE_B  = 128 * HROW_B;            // 10240
constexpr int B_TILE_B  = 256 * HROW_B;            // 20480
constexpr int H_STAGE   = A_TILE_B + B_TILE_B;     // 30720
constexpr int H_STAGES  = 3;
constexpr int GEMM_SMEM = H_STAGES * H_STAGE;      // 92160 B

template<typename OutT, bool RELU, bool BIAS>
__global__ __launch_bounds__(256, 1)
void gemm_mma(const __half* __restrict__ A, const __half* __restrict__ Bm,
              const float* __restrict__ bias, OutT* __restrict__ C,
              int M, int N, int K, int relu_cols)
{
    extern __shared__ char smem[];
    const int tid = threadIdx.x;
    const int m0 = blockIdx.y * 128;
    const int n0 = blockIdx.x * 256;
    const int KT = K >> 5;                         // chunks of 32 halfs

    const uint32_t smem_base = smem_u32(smem);

    auto load_stage = [&](int kt, int buf) {
        uint32_t ab = smem_base + buf * H_STAGE;
        uint32_t bb = ab + A_TILE_B;
        const __half* Asrc = A + (size_t)m0 * K + kt * 32;
        const __half* Bsrc = Bm + (size_t)n0 * K + kt * 32;
#pragma unroll
        for (int j = 0; j < 2; j++) {              // A: 512 chunks of 16B
            int o = tid + j * 256;
            int r = o >> 2, cc = o & 3;
            cp16(ab + (uint32_t)(r * HROW_B + cc * 16),
                 Asrc + (size_t)r * K + cc * 8);
        }
#pragma unroll
        for (int j = 0; j < 4; j++) {              // B: 1024 chunks of 16B
            int o = tid + j * 256;
            int r = o >> 2, cc = o & 3;
            cp16(bb + (uint32_t)(r * HROW_B + cc * 16),
                 Bsrc + (size_t)r * K + cc * 8);
        }
    };

    const int wid  = tid >> 5;
    const int lane = tid & 31;
    const int wm = wid & 1;                        // 0..1 (64 rows each)
    const int wn = wid >> 1;                       // 0..3 (64 cols each)
    const int g  = lane >> 2;
    const int tg = lane & 3;

    // ldmatrix base offsets (bytes within tile)
    // A: 16x16 tile -> x4: lanes 0-15 rows, lanes 16-31 +16B (k8 half)
    const uint32_t aoff = (uint32_t)((wm * 64 + (lane & 15)) * HROW_B
                                     + ((lane & 16) ? 16 : 0));
    // B: two n8 tiles per x4: groups {0,1} tile n+0 (k0,k8), {2,3} tile n+8
    const uint32_t boff = (uint32_t)((wn * 64 + ((lane & 16) ? 8 : 0)
                                      + (lane & 7)) * HROW_B
                                     + ((lane & 8) ? 16 : 0));

    float acc[4][8][4];
#pragma unroll
    for (int mi = 0; mi < 4; mi++)
#pragma unroll
        for (int ni = 0; ni < 8; ni++)
#pragma unroll
            for (int q = 0; q < 4; q++) acc[mi][ni][q] = 0.f;

    load_stage(0, 0);
    asm volatile("cp.async.commit_group;" ::: "memory");
    load_stage(1, 1);
    asm volatile("cp.async.commit_group;" ::: "memory");

    for (int kt = 0; kt < KT; kt++) {
        asm volatile("cp.async.wait_group 1;" ::: "memory");
        __syncthreads();

        if (kt + 2 < KT) load_stage(kt + 2, (kt + 2) % H_STAGES);
        asm volatile("cp.async.commit_group;" ::: "memory");

        uint32_t As = smem_base + (kt % H_STAGES) * H_STAGE;
        uint32_t Bs = As + A_TILE_B;

#pragma unroll
        for (int ks = 0; ks < 2; ks++) {
            uint32_t kofs = ks * 32;               // 16 halfs
            uint32_t af[4][4];
#pragma unroll
            for (int mi = 0; mi < 4; mi++)
                ldsm_x4(af[mi][0], af[mi][1], af[mi][2], af[mi][3],
                        As + aoff + mi * (16 * HROW_B) + kofs);
            uint32_t bf[8][2];
#pragma unroll
            for (int nj = 0; nj < 4; nj++)
                ldsm_x4(bf[nj * 2][0], bf[nj * 2][1],
                        bf[nj * 2 + 1][0], bf[nj * 2 + 1][1],
                        Bs + boff + nj * (16 * HROW_B) + kofs);
#pragma unroll
            for (int mi = 0; mi < 4; mi++)
#pragma unroll
                for (int ni = 0; ni < 8; ni++)
                    mma_f16(acc[mi][ni], af[mi][0], af[mi][1], af[mi][2],
                            af[mi][3], bf[ni][0], bf[ni][1]);
        }
        __syncthreads();
    }

    // ---- epilogue ----
#pragma unroll
    for (int mi = 0; mi < 4; mi++) {
        int row0 = m0 + wm * 64 + mi * 16 + g;
#pragma unroll
        for (int ni = 0; ni < 8; ni++) {
            int col = n0 + wn * 64 + ni * 8 + tg * 2;
            float2 v0 = make_float2(acc[mi][ni][0], acc[mi][ni][1]);
            float2 v1 = make_float2(acc[mi][ni][2], acc[mi][ni][3]);
            if (BIAS) {
                float2 b2 = *(const float2*)(bias + col);
                v0.x += b2.x; v0.y += b2.y;
                v1.x += b2.x; v1.y += b2.y;
            }
            if (RELU && col < relu_cols) {
                v0.x = fmaxf(v0.x, 0.f); v0.y = fmaxf(v0.y, 0.f);
                v1.x = fmaxf(v1.x, 0.f); v1.y = fmaxf(v1.y, 0.f);
            }
            if constexpr (sizeof(OutT) == 2) {
                *(half2*)((__half*)C + (size_t)row0 * N + col) =
                    __floats2half2_rn(v0.x, v0.y);
                *(half2*)((__half*)C + (size_t)(row0 + 8) * N + col) =
                    __floats2half2_rn(v1.x, v1.y);
            } else {
                *(float2*)((float*)C + (size_t)row0 * N + col) = v0;
                *(float2*)((float*)C + (size_t)(row0 + 8) * N + col) = v1;
            }
        }
    }
}

// ------------------------- K4: kv + ksum (split-K partials) -----------------
// PHIVH is fp16; convert on load, accumulate fp32.
__global__ __launch_bounds__(256)
void kv_kernel()
{
    int split = blockIdx.x;
    int bh = blockIdx.y;
    int b = bh >> 4, h = bh & 15;
    __shared__ float PK[64][68];
    __shared__ float VV[64][68];
    int tid = threadIdx.x;
    int ti = tid >> 4, tj = tid & 15;

    float acc[4][4];
#pragma unroll
    for (int i = 0; i < 4; i++)
#pragma unroll
        for (int j = 0; j < 4; j++) acc[i][j] = 0.f;
    float ks = 0.f;

    size_t base_row = (size_t)b * 4096 + split * 512;
    for (int c = 0; c < 8; c++) {
#pragma unroll
        for (int i = 0; i < 4; i++) {
            int f = tid + i * 256;
            int r = f >> 4, c4 = (f & 15) << 2;
            const __half* src = g_PHIVH + (base_row + c * 64 + r) * 3072;
            half2 p0 = *(const half2*)(src + 1024 + h * 64 + c4);
            half2 p1 = *(const half2*)(src + 1024 + h * 64 + c4 + 2);
            half2 q0 = *(const half2*)(src + 2048 + h * 64 + c4);
            half2 q1 = *(const half2*)(src + 2048 + h * 64 + c4 + 2);
            float2 fp0 = __half22float2(p0), fp1 = __half22float2(p1);
            float2 fq0 = __half22float2(q0), fq1 = __half22float2(q1);
            PK[r][c4] = fp0.x; PK[r][c4 + 1] = fp0.y;
            PK[r][c4 + 2] = fp1.x; PK[r][c4 + 3] = fp1.y;
            VV[r][c4] = fq0.x; VV[r][c4 + 1] = fq0.y;
            VV[r][c4 + 2] = fq1.x; VV[r][c4 + 3] = fq1.y;
        }
        __syncthreads();
#pragma unroll 8
        for (int n = 0; n < 64; n++) {
            float4 a  = *(float4*)&PK[n][ti * 4];
            float4 bb = *(float4*)&VV[n][tj * 4];
            float av[4] = {a.x, a.y, a.z, a.w};
            float bv[4] = {bb.x, bb.y, bb.z, bb.w};
#pragma unroll
            for (int i = 0; i < 4; i++)
#pragma unroll
                for (int j = 0; j < 4; j++)
                    acc[i][j] += av[i] * bv[j];
        }
        if (tid < 64) {
#pragma unroll 8
            for (int n = 0; n < 64; n++) ks += PK[n][tid];
        }
        __syncthreads();
    }
    float* dst = g_KVP + (size_t)(split * 64 + bh) * 4096;
#pragma unroll
    for (int i = 0; i < 4; i++)
#pragma unroll
        for (int j = 0; j < 4; j++)
            dst[(ti * 4 + i) * 64 + tj * 4 + j] = acc[i][j];
    if (tid < 64) g_KSP[(split * 64 + bh) * 64 + tid] = ks;
}

// ------------------------- K5: deterministic reduction ----------------------
__global__ __launch_bounds__(256)
void kv_reduce_kernel()
{
    int idx = blockIdx.x * 256 + threadIdx.x;
    if (idx < 64 * 4096) {
        int bh = idx >> 12, r = idx & 4095;
        float s = 0.f;
#pragma unroll
        for (int sp = 0; sp < 8; sp++)
            s += g_KVP[(size_t)(sp * 64 + bh) * 4096 + r];
        g_KV[idx] = s;
    } else {
        int j = idx - 64 * 4096;
        if (j < 64 * 64) {
            int bh = j >> 6, d = j & 63;
            float s = 0.f;
#pragma unroll
            for (int sp = 0; sp < 8; sp++)
                s += g_KSP[(sp * 64 + bh) * 64 + d];
            g_KSUM[j] = s;
        }
    }
}

// ------------------------- K6: attn = inv * phiQ @ kv (fp16 out) ------------
__global__ __launch_bounds__(256)
void attn_kernel()
{
    int chunkb = blockIdx.x;
    int bh = blockIdx.y;
    int b = bh >> 4, h = bh & 15;
    __shared__ float KVs[64][64];
    __shared__ float KSs[64];
    int tid = threadIdx.x;
#pragma unroll
    for (int i = 0; i < 4; i++) {
        int f = tid + i * 256;
        *(float4*)&KVs[f >> 4][(f & 15) << 2] =
            *(const float4*)(g_KV + (size_t)bh * 4096 + f * 4);
    }
    if (tid < 64) KSs[tid] = g_KSUM[bh * 64 + tid];
    __syncthreads();

    int r = tid >> 1, halfsel = tid & 1;
    size_t m = (size_t)b * 4096 + chunkb * 128 + r;
    const __half* phq = g_PHIVH + m * 3072 + h * 64;

    float acc[32];
#pragma unroll
    for (int j = 0; j < 32; j++) acc[j] = 0.f;
    float denom = 0.f;

#pragma unroll
    for (int d0 = 0; d0 < 64; d0 += 16) {
        float q[16];
#pragma unroll
        for (int i = 0; i < 8; i++) {
            float2 t = __half22float2(*(const half2*)(phq + d0 + i * 2));
            q[i * 2] = t.x; q[i * 2 + 1] = t.y;
        }
#pragma unroll
        for (int dd = 0; dd < 16; dd++) {
            int d = d0 + dd;
            float p = q[dd];
            denom += p * KSs[d];
#pragma unroll
            for (int j = 0; j < 32; j += 4) {
                float4 kvv = *(float4*)&KVs[d][halfsel * 32 + j];
                acc[j]     += p * kvv.x;
                acc[j + 1] += p * kvv.y;
                acc[j + 2] += p * kvv.z;
                acc[j + 3] += p * kvv.w;
            }
        }
    }
    float inv = 1.0f / (0.125f * denom + 1e-8f);
    __half* dst = g_ATTNH + m * 1024 + h * 64 + halfsel * 32;
#pragma unroll
    for (int j = 0; j < 32; j += 2)
        *(half2*)(dst + j) = __floats2half2_rn(acc[j] * inv, acc[j + 1] * inv);
}

// ------------------------- launch -------------------------------------------
extern "C" void kernel_launch(void* const* d_in, const int* in_sizes, int n_in,
                              void* d_out, int out_size)
{
    const float* query = (const float*)d_in[0];
    const float* Wq    = (const float*)d_in[1];
    const float* Wk    = (const float*)d_in[2];
    const float* Wv    = (const float*)d_in[3];
    const float* P     = (const float*)d_in[4];
    const float* Wo    = (const float*)d_in[5];
    const float* bo    = (const float*)d_in[6];
    float* out = (float*)d_out;

    void *p_xh, *p_wbigh, *p_worh, *p_attnh, *p_phivh;
    cudaGetSymbolAddress(&p_xh,     g_XH);
    cudaGetSymbolAddress(&p_wbigh,  g_WBIGH);
    cudaGetSymbolAddress(&p_worh,   g_WORH);
    cudaGetSymbolAddress(&p_attnh,  g_ATTNH);
    cudaGetSymbolAddress(&p_phivh,  g_PHIVH);

    cudaFuncSetAttribute((const void*)gemm_mma<__half, true, false>,
                         cudaFuncAttributeMaxDynamicSharedMemorySize, GEMM_SMEM);
    cudaFuncSetAttribute((const void*)gemm_mma<float, false, true>,
                         cudaFuncAttributeMaxDynamicSharedMemorySize, GEMM_SMEM);

    build_weff_kernel<<<512, 256>>>(Wq, Wk, P);
    copy_wv_kernel<<<1024, 256>>>(Wv);
    round_half_kernel<<<16384, 256>>>(query, (__half*)p_xh);
    round_half_kernel<<<1024, 256>>>(Wo, (__half*)p_worh);

    // PHIVH = relu(XH @ WBIGH^T) on first 2048 cols (fp16 out)
    gemm_mma<__half, true, false><<<dim3(12, 128), 256, GEMM_SMEM>>>(
        (const __half*)p_xh, (const __half*)p_wbigh, nullptr,
        (__half*)p_phivh, 16384, 3072, 1024, 2048);

    kv_kernel<<<dim3(8, 64), 256>>>();
    kv_reduce_kernel<<<1040, 256>>>();
    attn_kernel<<<dim3(32, 64), 256>>>();   // writes fp16 ATTN

    // out = ATTNH @ WORH^T + bo (fp32 out)
    gemm_mma<float, false, true><<<dim3(4, 128), 256, GEMM_SMEM>>>(
        (const __half*)p_attnh, (const __half*)p_worh, bo, out,
        16384, 1024, 1024, 0);
}

// round 6
// speedup vs baseline: 1.0840x; 1.0840x over previous
#include <cuda_runtime.h>
#include <cuda_fp16.h>
#include <cstdint>

// ---------------------------------------------------------------------------
// FastAttention — linear attention with ReLU feature maps.
// Big GEMMs: fp16 mma.sync m16n8k16, CTA tile 128x128x32, warp tile 64x32,
// 3-stage cp.async, 2 CTAs/SM. PHIV intermediate fp16. fp32 accumulation.
//
//   K1 build_weff : fold per-head orth proj into Wq/Wk -> g_WBIGH (fp16)
//   K2 copy_wv    : append Wv rows (fp16)
//   R1 round      : query -> g_XH (fp16)
//   R2 round      : Wo -> g_WORH (fp16)
//   G1 gemm_mma   : PHIVH[16384,3072](fp16) = XH @ WBIGH^T, relu cols [0,2048)
//   K4 kv_kernel  : split-K partial kv[64x64] + ksum[64] per (b,h)
//   K5 kv_reduce  : deterministic reduction
//   K6 attn_kernel: attn = inv * phiQ @ kv -> g_ATTNH (fp16)
//   G2 gemm_mma   : out(fp32) = ATTNH @ WORH^T + bo
// ---------------------------------------------------------------------------

// ------------------------- device scratch (no allocs) ----------------------
__device__ __align__(16) __half g_XH[(size_t)16384 * 1024];
__device__ __align__(16) __half g_WBIGH[(size_t)3072 * 1024];
__device__ __align__(16) __half g_WORH[(size_t)1024 * 1024];
__device__ __align__(16) __half g_ATTNH[(size_t)16384 * 1024];
__device__ __align__(16) __half g_PHIVH[(size_t)16384 * 3072];
__device__ float g_KV[64 * 64 * 64];
__device__ float g_KSUM[64 * 64];
__device__ float g_KVP[8 * 64 * 64 * 64];
__device__ float g_KSP[8 * 64 * 64];

// ------------------------- helpers ------------------------------------------
__device__ __forceinline__ uint32_t smem_u32(const void* p) {
    uint32_t a;
    asm("{ .reg .u64 t; cvta.to.shared.u64 t, %1; cvt.u32.u64 %0, t; }"
        : "=r"(a) : "l"(p));
    return a;
}
__device__ __forceinline__ void cp16(uint32_t dst, const void* src) {
    asm volatile("cp.async.cg.shared.global [%0], [%1], 16;" :: "r"(dst), "l"(src));
}
__device__ __forceinline__ void ldsm_x4(uint32_t& r0, uint32_t& r1,
                                        uint32_t& r2, uint32_t& r3, uint32_t a) {
    asm volatile("ldmatrix.sync.aligned.m8n8.x4.shared.b16 {%0,%1,%2,%3}, [%4];"
                 : "=r"(r0), "=r"(r1), "=r"(r2), "=r"(r3) : "r"(a));
}
__device__ __forceinline__ void ldsm_x2(uint32_t& r0, uint32_t& r1, uint32_t a) {
    asm volatile("ldmatrix.sync.aligned.m8n8.x2.shared.b16 {%0,%1}, [%2];"
                 : "=r"(r0), "=r"(r1) : "r"(a));
}
__device__ __forceinline__ void mma_f16(float* c, uint32_t a0, uint32_t a1,
                                        uint32_t a2, uint32_t a3,
                                        uint32_t b0, uint32_t b1) {
    asm volatile(
        "mma.sync.aligned.m16n8k16.row.col.f32.f16.f16.f32 "
        "{%0,%1,%2,%3}, {%4,%5,%6,%7}, {%8,%9}, {%0,%1,%2,%3};"
        : "+f"(c[0]), "+f"(c[1]), "+f"(c[2]), "+f"(c[3])
        : "r"(a0), "r"(a1), "r"(a2), "r"(a3), "r"(b0), "r"(b1));
}

// ------------------------- K1: fused per-head weights (fp16 out) ------------
__global__ __launch_bounds__(256)
void build_weff_kernel(const float* __restrict__ Wq,
                       const float* __restrict__ Wk,
                       const float* __restrict__ P)
{
    int bid   = blockIdx.x;
    int which = bid >> 8;
    int rem   = bid & 255;
    int h     = rem >> 4;
    int chunk = rem & 15;
    const float* W = which ? Wk : Wq;

    __shared__ float Psh[64][64];
    __shared__ float Wsh[64][64];
    int tid = threadIdx.x;

#pragma unroll
    for (int i = 0; i < 4; i++) {
        int f = tid + i * 256;
        int e = f >> 4, c4 = (f & 15) << 2;
        *(float4*)&Psh[e][c4] = *(const float4*)(P + (size_t)h * 4096 + f * 4);
        *(float4*)&Wsh[e][c4] =
            *(const float4*)(W + (size_t)(h * 64 + e) * 1024 + chunk * 64 + c4);
    }
    __syncthreads();

    int dp = tid & 63;
    int dg = tid >> 6;
    float acc[16];
#pragma unroll
    for (int j = 0; j < 16; j++) acc[j] = 0.f;
#pragma unroll 4
    for (int e = 0; e < 64; e++) {
        float p = Psh[e][dp];
#pragma unroll
        for (int j = 0; j < 16; j++)
            acc[j] += p * Wsh[e][dg * 16 + j];
    }
    __half* dst = g_WBIGH + (size_t)(which * 1024 + h * 64 + dp) * 1024
                          + chunk * 64 + dg * 16;
#pragma unroll
    for (int j = 0; j < 16; j += 2)
        *(half2*)(dst + j) = __floats2half2_rn(acc[j], acc[j + 1]);
}

// ------------------------- K2: copy Wv (fp16) --------------------------------
__global__ __launch_bounds__(256)
void copy_wv_kernel(const float* __restrict__ Wv)
{
    int row = blockIdx.x;
    int tid = threadIdx.x;
    float4 v = *(const float4*)(Wv + (size_t)row * 1024 + tid * 4);
    __half* dst = g_WBIGH + (size_t)(2048 + row) * 1024 + tid * 4;
    *(half2*)(dst)     = __floats2half2_rn(v.x, v.y);
    *(half2*)(dst + 2) = __floats2half2_rn(v.z, v.w);
}

// ------------------------- round fp32 -> fp16 --------------------------------
__global__ __launch_bounds__(256)
void round_half_kernel(const float* __restrict__ src, __half* __restrict__ dst)
{
    size_t i = ((size_t)blockIdx.x * 256 + threadIdx.x) * 4;
    float4 v = *(const float4*)(src + i);
    *(half2*)(dst + i)     = __floats2half2_rn(v.x, v.y);
    *(half2*)(dst + i + 2) = __floats2half2_rn(v.z, v.w);
}

// ------------------------- fp16 mma GEMM (R4 config) ------------------------
// C[M,N] = A[M,K] @ B[N,K]^T (+bias, +relu on cols < relu_cols)
// CTA tile 128x128x32, 256 threads (8 warps 2x4), warp tile 64x32.
// 3-stage cp.async ring; SMEM rows 32 halfs + pad -> 80B stride.
constexpr int HROW_B   = 80;
constexpr int H_TILE_B = 128 * HROW_B;             // 10240 B per A/B tile
constexpr int H_STAGE  = 2 * H_TILE_B;             // 20480
constexpr int H_STAGES = 3;
constexpr int GEMM_SMEM = H_STAGES * H_STAGE;      // 61440 B (occ 2)

template<typename OutT, bool RELU, bool BIAS>
__global__ __launch_bounds__(256, 2)
void gemm_mma(const __half* __restrict__ A, const __half* __restrict__ Bm,
              const float* __restrict__ bias, OutT* __restrict__ C,
              int M, int N, int K, int relu_cols)
{
    extern __shared__ char smem[];
    const int tid = threadIdx.x;
    const int m0 = blockIdx.y * 128;
    const int n0 = blockIdx.x * 128;
    const int KT = K >> 5;                         // chunks of 32 halfs

    const uint32_t smem_base = smem_u32(smem);

    auto load_stage = [&](int kt, int buf) {
        uint32_t ab = smem_base + buf * H_STAGE;
        uint32_t bb = ab + H_TILE_B;
        const __half* Asrc = A + (size_t)m0 * K + kt * 32;
        const __half* Bsrc = Bm + (size_t)n0 * K + kt * 32;
#pragma unroll
        for (int j = 0; j < 2; j++) {              // 512 chunks each / 256 thr
            int o = tid + j * 256;
            int r = o >> 2, cc = o & 3;
            cp16(ab + (uint32_t)(r * HROW_B + cc * 16),
                 Asrc + (size_t)r * K + cc * 8);
            cp16(bb + (uint32_t)(r * HROW_B + cc * 16),
                 Bsrc + (size_t)r * K + cc * 8);
        }
    };

    const int wid  = tid >> 5;
    const int lane = tid & 31;
    const int wm = wid & 1;                        // 0..1 (64 rows)
    const int wn = wid >> 1;                       // 0..3 (32 cols)
    const int g  = lane >> 2;
    const int tg = lane & 3;

    const uint32_t aoff = (uint32_t)((wm * 64 + (lane & 15)) * HROW_B
                                     + ((lane & 16) ? 16 : 0));
    const uint32_t boff = (uint32_t)((wn * 32 + (lane & 7)) * HROW_B
                                     + ((lane & 8) ? 16 : 0));

    float acc[4][4][4];
#pragma unroll
    for (int mi = 0; mi < 4; mi++)
#pragma unroll
        for (int ni = 0; ni < 4; ni++)
#pragma unroll
            for (int q = 0; q < 4; q++) acc[mi][ni][q] = 0.f;

    load_stage(0, 0);
    asm volatile("cp.async.commit_group;" ::: "memory");
    load_stage(1, 1);
    asm volatile("cp.async.commit_group;" ::: "memory");

    for (int kt = 0; kt < KT; kt++) {
        asm volatile("cp.async.wait_group 1;" ::: "memory");
        __syncthreads();

        if (kt + 2 < KT) load_stage(kt + 2, (kt + 2) % H_STAGES);
        asm volatile("cp.async.commit_group;" ::: "memory");

        uint32_t As = smem_base + (kt % H_STAGES) * H_STAGE;
        uint32_t Bs = As + H_TILE_B;

#pragma unroll
        for (int ks = 0; ks < 2; ks++) {
            uint32_t kofs = ks * 32;               // 16 halfs = 32 B
            uint32_t af[4][4];
#pragma unroll
            for (int mi = 0; mi < 4; mi++)
                ldsm_x4(af[mi][0], af[mi][1], af[mi][2], af[mi][3],
                        As + aoff + mi * (16 * HROW_B) + kofs);
            uint32_t bf[4][2];
#pragma unroll
            for (int ni = 0; ni < 4; ni++)
                ldsm_x2(bf[ni][0], bf[ni][1],
                        Bs + boff + ni * (8 * HROW_B) + kofs);
#pragma unroll
            for (int mi = 0; mi < 4; mi++)
#pragma unroll
                for (int ni = 0; ni < 4; ni++)
                    mma_f16(acc[mi][ni], af[mi][0], af[mi][1], af[mi][2],
                            af[mi][3], bf[ni][0], bf[ni][1]);
        }
        __syncthreads();
    }

    // ---- epilogue ----
#pragma unroll
    for (int mi = 0; mi < 4; mi++) {
        int row0 = m0 + wm * 64 + mi * 16 + g;
#pragma unroll
        for (int ni = 0; ni < 4; ni++) {
            int col = n0 + wn * 32 + ni * 8 + tg * 2;
            float2 v0 = make_float2(acc[mi][ni][0], acc[mi][ni][1]);
            float2 v1 = make_float2(acc[mi][ni][2], acc[mi][ni][3]);
            if (BIAS) {
                float2 b2 = *(const float2*)(bias + col);
                v0.x += b2.x; v0.y += b2.y;
                v1.x += b2.x; v1.y += b2.y;
            }
            if (RELU && col < relu_cols) {
                v0.x = fmaxf(v0.x, 0.f); v0.y = fmaxf(v0.y, 0.f);
                v1.x = fmaxf(v1.x, 0.f); v1.y = fmaxf(v1.y, 0.f);
            }
            if constexpr (sizeof(OutT) == 2) {
                *(half2*)((__half*)C + (size_t)row0 * N + col) =
                    __floats2half2_rn(v0.x, v0.y);
                *(half2*)((__half*)C + (size_t)(row0 + 8) * N + col) =
                    __floats2half2_rn(v1.x, v1.y);
            } else {
                *(float2*)((float*)C + (size_t)row0 * N + col) = v0;
                *(float2*)((float*)C + (size_t)(row0 + 8) * N + col) = v1;
            }
        }
    }
}

// ------------------------- K4: kv + ksum (split-K partials) -----------------
// PHIVH is fp16; convert on load, accumulate fp32.
__global__ __launch_bounds__(256)
void kv_kernel()
{
    int split = blockIdx.x;
    int bh = blockIdx.y;
    int b = bh >> 4, h = bh & 15;
    __shared__ float PK[64][68];
    __shared__ float VV[64][68];
    int tid = threadIdx.x;
    int ti = tid >> 4, tj = tid & 15;

    float acc[4][4];
#pragma unroll
    for (int i = 0; i < 4; i++)
#pragma unroll
        for (int j = 0; j < 4; j++) acc[i][j] = 0.f;
    float ks = 0.f;

    size_t base_row = (size_t)b * 4096 + split * 512;
    for (int c = 0; c < 8; c++) {
#pragma unroll
        for (int i = 0; i < 4; i++) {
            int f = tid + i * 256;
            int r = f >> 4, c4 = (f & 15) << 2;
            const __half* src = g_PHIVH + (base_row + c * 64 + r) * 3072;
            half2 p0 = *(const half2*)(src + 1024 + h * 64 + c4);
            half2 p1 = *(const half2*)(src + 1024 + h * 64 + c4 + 2);
            half2 q0 = *(const half2*)(src + 2048 + h * 64 + c4);
            half2 q1 = *(const half2*)(src + 2048 + h * 64 + c4 + 2);
            float2 fp0 = __half22float2(p0), fp1 = __half22float2(p1);
            float2 fq0 = __half22float2(q0), fq1 = __half22float2(q1);
            PK[r][c4] = fp0.x; PK[r][c4 + 1] = fp0.y;
            PK[r][c4 + 2] = fp1.x; PK[r][c4 + 3] = fp1.y;
            VV[r][c4] = fq0.x; VV[r][c4 + 1] = fq0.y;
            VV[r][c4 + 2] = fq1.x; VV[r][c4 + 3] = fq1.y;
        }
        __syncthreads();
#pragma unroll 8
        for (int n = 0; n < 64; n++) {
            float4 a  = *(float4*)&PK[n][ti * 4];
            float4 bb = *(float4*)&VV[n][tj * 4];
            float av[4] = {a.x, a.y, a.z, a.w};
            float bv[4] = {bb.x, bb.y, bb.z, bb.w};
#pragma unroll
            for (int i = 0; i < 4; i++)
#pragma unroll
                for (int j = 0; j < 4; j++)
                    acc[i][j] += av[i] * bv[j];
        }
        if (tid < 64) {
#pragma unroll 8
            for (int n = 0; n < 64; n++) ks += PK[n][tid];
        }
        __syncthreads();
    }
    float* dst = g_KVP + (size_t)(split * 64 + bh) * 4096;
#pragma unroll
    for (int i = 0; i < 4; i++)
#pragma unroll
        for (int j = 0; j < 4; j++)
            dst[(ti * 4 + i) * 64 + tj * 4 + j] = acc[i][j];
    if (tid < 64) g_KSP[(split * 64 + bh) * 64 + tid] = ks;
}

// ------------------------- K5: deterministic reduction ----------------------
__global__ __launch_bounds__(256)
void kv_reduce_kernel()
{
    int idx = blockIdx.x * 256 + threadIdx.x;
    if (idx < 64 * 4096) {
        int bh = idx >> 12, r = idx & 4095;
        float s = 0.f;
#pragma unroll
        for (int sp = 0; sp < 8; sp++)
            s += g_KVP[(size_t)(sp * 64 + bh) * 4096 + r];
        g_KV[idx] = s;
    } else {
        int j = idx - 64 * 4096;
        if (j < 64 * 64) {
            int bh = j >> 6, d = j & 63;
            float s = 0.f;
#pragma unroll
            for (int sp = 0; sp < 8; sp++)
                s += g_KSP[(sp * 64 + bh) * 64 + d];
            g_KSUM[j] = s;
        }
    }
}

// ------------------------- K6: attn = inv * phiQ @ kv (fp16 out) ------------
__global__ __launch_bounds__(256)
void attn_kernel()
{
    int chunkb = blockIdx.x;
    int bh = blockIdx.y;
    int b = bh >> 4, h = bh & 15;
    __shared__ float KVs[64][64];
    __shared__ float KSs[64];
    int tid = threadIdx.x;
#pragma unroll
    for (int i = 0; i < 4; i++) {
        int f = tid + i * 256;
        *(float4*)&KVs[f >> 4][(f & 15) << 2] =
            *(const float4*)(g_KV + (size_t)bh * 4096 + f * 4);
    }
    if (tid < 64) KSs[tid] = g_KSUM[bh * 64 + tid];
    __syncthreads();

    int r = tid >> 1, halfsel = tid & 1;
    size_t m = (size_t)b * 4096 + chunkb * 128 + r;
    const __half* phq = g_PHIVH + m * 3072 + h * 64;

    float acc[32];
#pragma unroll
    for (int j = 0; j < 32; j++) acc[j] = 0.f;
    float denom = 0.f;

#pragma unroll
    for (int d0 = 0; d0 < 64; d0 += 16) {
        float q[16];
#pragma unroll
        for (int i = 0; i < 8; i++) {
            float2 t = __half22float2(*(const half2*)(phq + d0 + i * 2));
            q[i * 2] = t.x; q[i * 2 + 1] = t.y;
        }
#pragma unroll
        for (int dd = 0; dd < 16; dd++) {
            int d = d0 + dd;
            float p = q[dd];
            denom += p * KSs[d];
#pragma unroll
            for (int j = 0; j < 32; j += 4) {
                float4 kvv = *(float4*)&KVs[d][halfsel * 32 + j];
                acc[j]     += p * kvv.x;
                acc[j + 1] += p * kvv.y;
                acc[j + 2] += p * kvv.z;
                acc[j + 3] += p * kvv.w;
            }
        }
    }
    float inv = 1.0f / (0.125f * denom + 1e-8f);
    __half* dst = g_ATTNH + m * 1024 + h * 64 + halfsel * 32;
#pragma unroll
    for (int j = 0; j < 32; j += 2)
        *(half2*)(dst + j) = __floats2half2_rn(acc[j] * inv, acc[j + 1] * inv);
}

// ------------------------- launch -------------------------------------------
extern "C" void kernel_launch(void* const* d_in, const int* in_sizes, int n_in,
                              void* d_out, int out_size)
{
    const float* query = (const float*)d_in[0];
    const float* Wq    = (const float*)d_in[1];
    const float* Wk    = (const float*)d_in[2];
    const float* Wv    = (const float*)d_in[3];
    const float* P     = (const float*)d_in[4];
    const float* Wo    = (const float*)d_in[5];
    const float* bo    = (const float*)d_in[6];
    float* out = (float*)d_out;

    void *p_xh, *p_wbigh, *p_worh, *p_attnh, *p_phivh;
    cudaGetSymbolAddress(&p_xh,     g_XH);
    cudaGetSymbolAddress(&p_wbigh,  g_WBIGH);
    cudaGetSymbolAddress(&p_worh,   g_WORH);
    cudaGetSymbolAddress(&p_attnh,  g_ATTNH);
    cudaGetSymbolAddress(&p_phivh,  g_PHIVH);

    cudaFuncSetAttribute((const void*)gemm_mma<__half, true, false>,
                         cudaFuncAttributeMaxDynamicSharedMemorySize, GEMM_SMEM);
    cudaFuncSetAttribute((const void*)gemm_mma<float, false, true>,
                         cudaFuncAttributeMaxDynamicSharedMemorySize, GEMM_SMEM);

    build_weff_kernel<<<512, 256>>>(Wq, Wk, P);
    copy_wv_kernel<<<1024, 256>>>(Wv);
    round_half_kernel<<<16384, 256>>>(query, (__half*)p_xh);
    round_half_kernel<<<1024, 256>>>(Wo, (__half*)p_worh);

    // PHIVH = relu(XH @ WBIGH^T) on first 2048 cols (fp16 out)
    gemm_mma<__half, true, false><<<dim3(24, 128), 256, GEMM_SMEM>>>(
        (const __half*)p_xh, (const __half*)p_wbigh, nullptr,
        (__half*)p_phivh, 16384, 3072, 1024, 2048);

    kv_kernel<<<dim3(8, 64), 256>>>();
    kv_reduce_kernel<<<1040, 256>>>();
    attn_kernel<<<dim3(32, 64), 256>>>();   // writes fp16 ATTN

    // out = ATTNH @ WORH^T + bo (fp32 out)
    gemm_mma<float, false, true><<<dim3(8, 128), 256, GEMM_SMEM>>>(
        (const __half*)p_attnh, (const __half*)p_worh, bo, out,
        16384, 1024, 1024, 0);
}

// round 7
// speedup vs baseline: 1.2239x; 1.1291x over previous
#include <cuda_runtime.h>
#include <cuda_fp16.h>
#include <cstdint>

// ---------------------------------------------------------------------------
// FastAttention — linear attention with ReLU feature maps.
// Big GEMMs: fp16 mma.sync m16n8k16, CTA tile 128x128x32 with 128 threads
// (4 warps, warp tile 64x64), 4-stage cp.async, 1 sync/iter, 2 CTAs/SM.
// PHIV intermediate fp16. fp32 accumulation everywhere.
// ---------------------------------------------------------------------------

// ------------------------- device scratch (no allocs) ----------------------
__device__ __align__(16) __half g_XH[(size_t)16384 * 1024];
__device__ __align__(16) __half g_WBIGH[(size_t)3072 * 1024];
__device__ __align__(16) __half g_WORH[(size_t)1024 * 1024];
__device__ __align__(16) __half g_ATTNH[(size_t)16384 * 1024];
__device__ __align__(16) __half g_PHIVH[(size_t)16384 * 3072];
__device__ float g_KV[64 * 64 * 64];
__device__ float g_KSUM[64 * 64];
__device__ float g_KVP[8 * 64 * 64 * 64];
__device__ float g_KSP[8 * 64 * 64];

// ------------------------- helpers ------------------------------------------
__device__ __forceinline__ uint32_t smem_u32(const void* p) {
    uint32_t a;
    asm("{ .reg .u64 t; cvta.to.shared.u64 t, %1; cvt.u32.u64 %0, t; }"
        : "=r"(a) : "l"(p));
    return a;
}
__device__ __forceinline__ void cp16(uint32_t dst, const void* src) {
    asm volatile("cp.async.cg.shared.global [%0], [%1], 16;" :: "r"(dst), "l"(src));
}
__device__ __forceinline__ void ldsm_x4(uint32_t& r0, uint32_t& r1,
                                        uint32_t& r2, uint32_t& r3, uint32_t a) {
    asm volatile("ldmatrix.sync.aligned.m8n8.x4.shared.b16 {%0,%1,%2,%3}, [%4];"
                 : "=r"(r0), "=r"(r1), "=r"(r2), "=r"(r3) : "r"(a));
}
__device__ __forceinline__ void mma_f16(float* c, uint32_t a0, uint32_t a1,
                                        uint32_t a2, uint32_t a3,
                                        uint32_t b0, uint32_t b1) {
    asm volatile(
        "mma.sync.aligned.m16n8k16.row.col.f32.f16.f16.f32 "
        "{%0,%1,%2,%3}, {%4,%5,%6,%7}, {%8,%9}, {%0,%1,%2,%3};"
        : "+f"(c[0]), "+f"(c[1]), "+f"(c[2]), "+f"(c[3])
        : "r"(a0), "r"(a1), "r"(a2), "r"(a3), "r"(b0), "r"(b1));
}

// ------------------------- K1: fused per-head weights (fp16 out) ------------
__global__ __launch_bounds__(256)
void build_weff_kernel(const float* __restrict__ Wq,
                       const float* __restrict__ Wk,
                       const float* __restrict__ P)
{
    int bid   = blockIdx.x;
    int which = bid >> 8;
    int rem   = bid & 255;
    int h     = rem >> 4;
    int chunk = rem & 15;
    const float* W = which ? Wk : Wq;

    __shared__ float Psh[64][64];
    __shared__ float Wsh[64][64];
    int tid = threadIdx.x;

#pragma unroll
    for (int i = 0; i < 4; i++) {
        int f = tid + i * 256;
        int e = f >> 4, c4 = (f & 15) << 2;
        *(float4*)&Psh[e][c4] = *(const float4*)(P + (size_t)h * 4096 + f * 4);
        *(float4*)&Wsh[e][c4] =
            *(const float4*)(W + (size_t)(h * 64 + e) * 1024 + chunk * 64 + c4);
    }
    __syncthreads();

    int dp = tid & 63;
    int dg = tid >> 6;
    float acc[16];
#pragma unroll
    for (int j = 0; j < 16; j++) acc[j] = 0.f;
#pragma unroll 4
    for (int e = 0; e < 64; e++) {
        float p = Psh[e][dp];
#pragma unroll
        for (int j = 0; j < 16; j++)
            acc[j] += p * Wsh[e][dg * 16 + j];
    }
    __half* dst = g_WBIGH + (size_t)(which * 1024 + h * 64 + dp) * 1024
                          + chunk * 64 + dg * 16;
#pragma unroll
    for (int j = 0; j < 16; j += 2)
        *(half2*)(dst + j) = __floats2half2_rn(acc[j], acc[j + 1]);
}

// ------------------------- K2: copy Wv (fp16) --------------------------------
__global__ __launch_bounds__(256)
void copy_wv_kernel(const float* __restrict__ Wv)
{
    int row = blockIdx.x;
    int tid = threadIdx.x;
    float4 v = *(const float4*)(Wv + (size_t)row * 1024 + tid * 4);
    __half* dst = g_WBIGH + (size_t)(2048 + row) * 1024 + tid * 4;
    *(half2*)(dst)     = __floats2half2_rn(v.x, v.y);
    *(half2*)(dst + 2) = __floats2half2_rn(v.z, v.w);
}

// ------------------------- round fp32 -> fp16 --------------------------------
__global__ __launch_bounds__(256)
void round_half_kernel(const float* __restrict__ src, __half* __restrict__ dst)
{
    size_t i = ((size_t)blockIdx.x * 256 + threadIdx.x) * 4;
    float4 v = *(const float4*)(src + i);
    *(half2*)(dst + i)     = __floats2half2_rn(v.x, v.y);
    *(half2*)(dst + i + 2) = __floats2half2_rn(v.z, v.w);
}

// ------------------------- fp16 mma GEMM ------------------------------------
// C[M,N] = A[M,K] @ B[N,K]^T (+bias, +relu on cols < relu_cols)
// CTA tile 128x128x32, 128 threads (4 warps 2x2), warp tile 64x64.
// 4-stage cp.async ring, single __syncthreads per k-iteration.
constexpr int HROW_B   = 80;                       // bytes per padded row
constexpr int H_TILE_B = 128 * HROW_B;             // 10240 B per A/B tile
constexpr int H_STAGE  = 2 * H_TILE_B;             // 20480
constexpr int H_STAGES = 4;
constexpr int GEMM_SMEM = H_STAGES * H_STAGE;      // 81920 B

template<typename OutT, bool RELU, bool BIAS>
__global__ __launch_bounds__(128, 2)
void gemm_mma(const __half* __restrict__ A, const __half* __restrict__ Bm,
              const float* __restrict__ bias, OutT* __restrict__ C,
              int M, int N, int K, int relu_cols)
{
    extern __shared__ char smem[];
    const int tid = threadIdx.x;
    const int m0 = blockIdx.y * 128;
    const int n0 = blockIdx.x * 128;
    const int KT = K >> 5;                         // chunks of 32 halfs

    const uint32_t smem_base = smem_u32(smem);

    auto load_stage = [&](int kt, int buf) {
        uint32_t ab = smem_base + buf * H_STAGE;
        uint32_t bb = ab + H_TILE_B;
        const __half* Asrc = A + (size_t)m0 * K + kt * 32;
        const __half* Bsrc = Bm + (size_t)n0 * K + kt * 32;
#pragma unroll
        for (int j = 0; j < 4; j++) {              // 512 chunks of 16B each
            int o = tid + j * 128;
            int r = o >> 2, cc = o & 3;
            cp16(ab + (uint32_t)(r * HROW_B + cc * 16),
                 Asrc + (size_t)r * K + cc * 8);
            cp16(bb + (uint32_t)(r * HROW_B + cc * 16),
                 Bsrc + (size_t)r * K + cc * 8);
        }
    };

    const int wid  = tid >> 5;
    const int lane = tid & 31;
    const int wm = wid & 1;                        // 0..1 (64 rows)
    const int wn = wid >> 1;                       // 0..1 (64 cols)
    const int g  = lane >> 2;
    const int tg = lane & 3;

    // A: 16x16 tiles via ldsm_x4 — lanes 0-15 rows, lanes 16-31 +16B (k8)
    const uint32_t aoff = (uint32_t)((wm * 64 + (lane & 15)) * HROW_B
                                     + ((lane & 16) ? 16 : 0));
    // B: two n8 tiles per ldsm_x4 (lanes 0-15 n+0 k0/k8, 16-31 n+8 k0/k8)
    const uint32_t boff = (uint32_t)((wn * 64 + ((lane & 16) ? 8 : 0)
                                      + (lane & 7)) * HROW_B
                                     + ((lane & 8) ? 16 : 0));

    float acc[4][8][4];
#pragma unroll
    for (int mi = 0; mi < 4; mi++)
#pragma unroll
        for (int ni = 0; ni < 8; ni++)
#pragma unroll
            for (int q = 0; q < 4; q++) acc[mi][ni][q] = 0.f;

    load_stage(0, 0);
    asm volatile("cp.async.commit_group;" ::: "memory");
    load_stage(1, 1);
    asm volatile("cp.async.commit_group;" ::: "memory");
    load_stage(2, 2);
    asm volatile("cp.async.commit_group;" ::: "memory");

    for (int kt = 0; kt < KT; kt++) {
        asm volatile("cp.async.wait_group 2;" ::: "memory");
        // One barrier: publishes stage kt arrivals to all warps AND
        // guarantees stage (kt+3)%4 (consumed at iter kt-1) is free.
        __syncthreads();

        if (kt + 3 < KT) load_stage(kt + 3, (kt + 3) & 3);
        asm volatile("cp.async.commit_group;" ::: "memory");

        uint32_t As = smem_base + (kt & 3) * H_STAGE;
        uint32_t Bs = As + H_TILE_B;

#pragma unroll
        for (int ks = 0; ks < 2; ks++) {
            uint32_t kofs = ks * 32;               // 16 halfs = 32 B
            uint32_t af[4][4];
#pragma unroll
            for (int mi = 0; mi < 4; mi++)
                ldsm_x4(af[mi][0], af[mi][1], af[mi][2], af[mi][3],
                        As + aoff + mi * (16 * HROW_B) + kofs);
            uint32_t bf[8][2];
#pragma unroll
            for (int nj = 0; nj < 4; nj++)
                ldsm_x4(bf[nj * 2][0], bf[nj * 2][1],
                        bf[nj * 2 + 1][0], bf[nj * 2 + 1][1],
                        Bs + boff + nj * (16 * HROW_B) + kofs);
#pragma unroll
            for (int mi = 0; mi < 4; mi++)
#pragma unroll
                for (int ni = 0; ni < 8; ni++)
                    mma_f16(acc[mi][ni], af[mi][0], af[mi][1], af[mi][2],
                            af[mi][3], bf[ni][0], bf[ni][1]);
        }
    }

    // ---- epilogue ----
#pragma unroll
    for (int mi = 0; mi < 4; mi++) {
        int row0 = m0 + wm * 64 + mi * 16 + g;
#pragma unroll
        for (int ni = 0; ni < 8; ni++) {
            int col = n0 + wn * 64 + ni * 8 + tg * 2;
            float2 v0 = make_float2(acc[mi][ni][0], acc[mi][ni][1]);
            float2 v1 = make_float2(acc[mi][ni][2], acc[mi][ni][3]);
            if (BIAS) {
                float2 b2 = *(const float2*)(bias + col);
                v0.x += b2.x; v0.y += b2.y;
                v1.x += b2.x; v1.y += b2.y;
            }
            if (RELU && col < relu_cols) {
                v0.x = fmaxf(v0.x, 0.f); v0.y = fmaxf(v0.y, 0.f);
                v1.x = fmaxf(v1.x, 0.f); v1.y = fmaxf(v1.y, 0.f);
            }
            if constexpr (sizeof(OutT) == 2) {
                *(half2*)((__half*)C + (size_t)row0 * N + col) =
                    __floats2half2_rn(v0.x, v0.y);
                *(half2*)((__half*)C + (size_t)(row0 + 8) * N + col) =
                    __floats2half2_rn(v1.x, v1.y);
            } else {
                *(float2*)((float*)C + (size_t)row0 * N + col) = v0;
                *(float2*)((float*)C + (size_t)(row0 + 8) * N + col) = v1;
            }
        }
    }
}

// ------------------------- K4: kv + ksum (split-K partials) -----------------
__global__ __launch_bounds__(256)
void kv_kernel()
{
    int split = blockIdx.x;
    int bh = blockIdx.y;
    int b = bh >> 4, h = bh & 15;
    __shared__ float PK[64][68];
    __shared__ float VV[64][68];
    int tid = threadIdx.x;
    int ti = tid >> 4, tj = tid & 15;

    float acc[4][4];
#pragma unroll
    for (int i = 0; i < 4; i++)
#pragma unroll
        for (int j = 0; j < 4; j++) acc[i][j] = 0.f;
    float ks = 0.f;

    size_t base_row = (size_t)b * 4096 + split * 512;
    for (int c = 0; c < 8; c++) {
#pragma unroll
        for (int i = 0; i < 4; i++) {
            int f = tid + i * 256;
            int r = f >> 4, c4 = (f & 15) << 2;
            const __half* src = g_PHIVH + (base_row + c * 64 + r) * 3072;
            half2 p0 = *(const half2*)(src + 1024 + h * 64 + c4);
            half2 p1 = *(const half2*)(src + 1024 + h * 64 + c4 + 2);
            half2 q0 = *(const half2*)(src + 2048 + h * 64 + c4);
            half2 q1 = *(const half2*)(src + 2048 + h * 64 + c4 + 2);
            float2 fp0 = __half22float2(p0), fp1 = __half22float2(p1);
            float2 fq0 = __half22float2(q0), fq1 = __half22float2(q1);
            PK[r][c4] = fp0.x; PK[r][c4 + 1] = fp0.y;
            PK[r][c4 + 2] = fp1.x; PK[r][c4 + 3] = fp1.y;
            VV[r][c4] = fq0.x; VV[r][c4 + 1] = fq0.y;
            VV[r][c4 + 2] = fq1.x; VV[r][c4 + 3] = fq1.y;
        }
        __syncthreads();
#pragma unroll 8
        for (int n = 0; n < 64; n++) {
            float4 a  = *(float4*)&PK[n][ti * 4];
            float4 bb = *(float4*)&VV[n][tj * 4];
            float av[4] = {a.x, a.y, a.z, a.w};
            float bv[4] = {bb.x, bb.y, bb.z, bb.w};
#pragma unroll
            for (int i = 0; i < 4; i++)
#pragma unroll
                for (int j = 0; j < 4; j++)
                    acc[i][j] += av[i] * bv[j];
        }
        if (tid < 64) {
#pragma unroll 8
            for (int n = 0; n < 64; n++) ks += PK[n][tid];
        }
        __syncthreads();
    }
    float* dst = g_KVP + (size_t)(split * 64 + bh) * 4096;
#pragma unroll
    for (int i = 0; i < 4; i++)
#pragma unroll
        for (int j = 0; j < 4; j++)
            dst[(ti * 4 + i) * 64 + tj * 4 + j] = acc[i][j];
    if (tid < 64) g_KSP[(split * 64 + bh) * 64 + tid] = ks;
}

// ------------------------- K5: deterministic reduction ----------------------
__global__ __launch_bounds__(256)
void kv_reduce_kernel()
{
    int idx = blockIdx.x * 256 + threadIdx.x;
    if (idx < 64 * 4096) {
        int bh = idx >> 12, r = idx & 4095;
        float s = 0.f;
#pragma unroll
        for (int sp = 0; sp < 8; sp++)
            s += g_KVP[(size_t)(sp * 64 + bh) * 4096 + r];
        g_KV[idx] = s;
    } else {
        int j = idx - 64 * 4096;
        if (j < 64 * 64) {
            int bh = j >> 6, d = j & 63;
            float s = 0.f;
#pragma unroll
            for (int sp = 0; sp < 8; sp++)
                s += g_KSP[(sp * 64 + bh) * 64 + d];
            g_KSUM[j] = s;
        }
    }
}

// ------------------------- K6: attn = inv * phiQ @ kv (fp16 out) ------------
__global__ __launch_bounds__(256)
void attn_kernel()
{
    int chunkb = blockIdx.x;
    int bh = blockIdx.y;
    int b = bh >> 4, h = bh & 15;
    __shared__ float KVs[64][64];
    __shared__ float KSs[64];
    int tid = threadIdx.x;
#pragma unroll
    for (int i = 0; i < 4; i++) {
        int f = tid + i * 256;
        *(float4*)&KVs[f >> 4][(f & 15) << 2] =
            *(const float4*)(g_KV + (size_t)bh * 4096 + f * 4);
    }
    if (tid < 64) KSs[tid] = g_KSUM[bh * 64 + tid];
    __syncthreads();

    int r = tid >> 1, halfsel = tid & 1;
    size_t m = (size_t)b * 4096 + chunkb * 128 + r;
    const __half* phq = g_PHIVH + m * 3072 + h * 64;

    float acc[32];
#pragma unroll
    for (int j = 0; j < 32; j++) acc[j] = 0.f;
    float denom = 0.f;

#pragma unroll
    for (int d0 = 0; d0 < 64; d0 += 16) {
        float q[16];
#pragma unroll
        for (int i = 0; i < 8; i++) {
            float2 t = __half22float2(*(const half2*)(phq + d0 + i * 2));
            q[i * 2] = t.x; q[i * 2 + 1] = t.y;
        }
#pragma unroll
        for (int dd = 0; dd < 16; dd++) {
            int d = d0 + dd;
            float p = q[dd];
            denom += p * KSs[d];
#pragma unroll
            for (int j = 0; j < 32; j += 4) {
                float4 kvv = *(float4*)&KVs[d][halfsel * 32 + j];
                acc[j]     += p * kvv.x;
                acc[j + 1] += p * kvv.y;
                acc[j + 2] += p * kvv.z;
                acc[j + 3] += p * kvv.w;
            }
        }
    }
    float inv = 1.0f / (0.125f * denom + 1e-8f);
    __half* dst = g_ATTNH + m * 1024 + h * 64 + halfsel * 32;
#pragma unroll
    for (int j = 0; j < 32; j += 2)
        *(half2*)(dst + j) = __floats2half2_rn(acc[j] * inv, acc[j + 1] * inv);
}

// ------------------------- launch -------------------------------------------
extern "C" void kernel_launch(void* const* d_in, const int* in_sizes, int n_in,
                              void* d_out, int out_size)
{
    const float* query = (const float*)d_in[0];
    const float* Wq    = (const float*)d_in[1];
    const float* Wk    = (const float*)d_in[2];
    const float* Wv    = (const float*)d_in[3];
    const float* P     = (const float*)d_in[4];
    const float* Wo    = (const float*)d_in[5];
    const float* bo    = (const float*)d_in[6];
    float* out = (float*)d_out;

    void *p_xh, *p_wbigh, *p_worh, *p_attnh, *p_phivh;
    cudaGetSymbolAddress(&p_xh,     g_XH);
    cudaGetSymbolAddress(&p_wbigh,  g_WBIGH);
    cudaGetSymbolAddress(&p_worh,   g_WORH);
    cudaGetSymbolAddress(&p_attnh,  g_ATTNH);
    cudaGetSymbolAddress(&p_phivh,  g_PHIVH);

    cudaFuncSetAttribute((const void*)gemm_mma<__half, true, false>,
                         cudaFuncAttributeMaxDynamicSharedMemorySize, GEMM_SMEM);
    cudaFuncSetAttribute((const void*)gemm_mma<float, false, true>,
                         cudaFuncAttributeMaxDynamicSharedMemorySize, GEMM_SMEM);

    build_weff_kernel<<<512, 256>>>(Wq, Wk, P);
    copy_wv_kernel<<<1024, 256>>>(Wv);
    round_half_kernel<<<16384, 256>>>(query, (__half*)p_xh);
    round_half_kernel<<<1024, 256>>>(Wo, (__half*)p_worh);

    // PHIVH = relu(XH @ WBIGH^T) on first 2048 cols (fp16 out)
    gemm_mma<__half, true, false><<<dim3(24, 128), 128, GEMM_SMEM>>>(
        (const __half*)p_xh, (const __half*)p_wbigh, nullptr,
        (__half*)p_phivh, 16384, 3072, 1024, 2048);

    kv_kernel<<<dim3(8, 64), 256>>>();
    kv_reduce_kernel<<<1040, 256>>>();
    attn_kernel<<<dim3(32, 64), 256>>>();   // writes fp16 ATTN

    // out = ATTNH @ WORH^T + bo (fp32 out)
    gemm_mma<float, false, true><<<dim3(8, 128), 128, GEMM_SMEM>>>(
        (const __half*)p_attnh, (const __half*)p_worh, bo, out,
        16384, 1024, 1024, 0);
}

// round 8
// speedup vs baseline: 1.3479x; 1.1014x over previous
#include <cuda_runtime.h>
#include <cuda_fp16.h>
#include <cstdint>

// ---------------------------------------------------------------------------
// FastAttention — linear attention with ReLU feature maps.
// Big GEMMs: fp16 mma.sync m16n8k16, CTA 128x128x32, 128 thr (warp 64x64),
// 4-stage cp.async, 1 sync/iter, 2 CTAs/SM.
// kv: fp16 mma via ldmatrix.trans (both operands transposed from [n,64]).
// PHIV intermediate fp16. fp32 accumulation everywhere.
// ---------------------------------------------------------------------------

// ------------------------- device scratch (no allocs) ----------------------
__device__ __align__(16) __half g_XH[(size_t)16384 * 1024];
__device__ __align__(16) __half g_WBIGH[(size_t)3072 * 1024];
__device__ __align__(16) __half g_WORH[(size_t)1024 * 1024];
__device__ __align__(16) __half g_ATTNH[(size_t)16384 * 1024];
__device__ __align__(16) __half g_PHIVH[(size_t)16384 * 3072];
__device__ float g_KV[64 * 64 * 64];
__device__ float g_KSUM[64 * 64];
__device__ float g_KVP[8 * 64 * 64 * 64];
__device__ float g_KSP[8 * 64 * 64];

// ------------------------- helpers ------------------------------------------
__device__ __forceinline__ uint32_t smem_u32(const void* p) {
    uint32_t a;
    asm("{ .reg .u64 t; cvta.to.shared.u64 t, %1; cvt.u32.u64 %0, t; }"
        : "=r"(a) : "l"(p));
    return a;
}
__device__ __forceinline__ void cp16(uint32_t dst, const void* src) {
    asm volatile("cp.async.cg.shared.global [%0], [%1], 16;" :: "r"(dst), "l"(src));
}
__device__ __forceinline__ void ldsm_x4(uint32_t& r0, uint32_t& r1,
                                        uint32_t& r2, uint32_t& r3, uint32_t a) {
    asm volatile("ldmatrix.sync.aligned.m8n8.x4.shared.b16 {%0,%1,%2,%3}, [%4];"
                 : "=r"(r0), "=r"(r1), "=r"(r2), "=r"(r3) : "r"(a));
}
__device__ __forceinline__ void ldsm_x4_t(uint32_t& r0, uint32_t& r1,
                                          uint32_t& r2, uint32_t& r3, uint32_t a) {
    asm volatile("ldmatrix.sync.aligned.m8n8.x4.trans.shared.b16 {%0,%1,%2,%3}, [%4];"
                 : "=r"(r0), "=r"(r1), "=r"(r2), "=r"(r3) : "r"(a));
}
__device__ __forceinline__ void mma_f16(float* c, uint32_t a0, uint32_t a1,
                                        uint32_t a2, uint32_t a3,
                                        uint32_t b0, uint32_t b1) {
    asm volatile(
        "mma.sync.aligned.m16n8k16.row.col.f32.f16.f16.f32 "
        "{%0,%1,%2,%3}, {%4,%5,%6,%7}, {%8,%9}, {%0,%1,%2,%3};"
        : "+f"(c[0]), "+f"(c[1]), "+f"(c[2]), "+f"(c[3])
        : "r"(a0), "r"(a1), "r"(a2), "r"(a3), "r"(b0), "r"(b1));
}

// ------------------------- K1: fused per-head weights (fp16 out) ------------
__global__ __launch_bounds__(256)
void build_weff_kernel(const float* __restrict__ Wq,
                       const float* __restrict__ Wk,
                       const float* __restrict__ P)
{
    int bid   = blockIdx.x;
    int which = bid >> 8;
    int rem   = bid & 255;
    int h     = rem >> 4;
    int chunk = rem & 15;
    const float* W = which ? Wk : Wq;

    __shared__ float Psh[64][64];
    __shared__ float Wsh[64][64];
    int tid = threadIdx.x;

#pragma unroll
    for (int i = 0; i < 4; i++) {
        int f = tid + i * 256;
        int e = f >> 4, c4 = (f & 15) << 2;
        *(float4*)&Psh[e][c4] = *(const float4*)(P + (size_t)h * 4096 + f * 4);
        *(float4*)&Wsh[e][c4] =
            *(const float4*)(W + (size_t)(h * 64 + e) * 1024 + chunk * 64 + c4);
    }
    __syncthreads();

    int dp = tid & 63;
    int dg = tid >> 6;
    float acc[16];
#pragma unroll
    for (int j = 0; j < 16; j++) acc[j] = 0.f;
#pragma unroll 4
    for (int e = 0; e < 64; e++) {
        float p = Psh[e][dp];
#pragma unroll
        for (int j = 0; j < 16; j++)
            acc[j] += p * Wsh[e][dg * 16 + j];
    }
    __half* dst = g_WBIGH + (size_t)(which * 1024 + h * 64 + dp) * 1024
                          + chunk * 64 + dg * 16;
#pragma unroll
    for (int j = 0; j < 16; j += 2)
        *(half2*)(dst + j) = __floats2half2_rn(acc[j], acc[j + 1]);
}

// ------------------------- K2: copy Wv (fp16) --------------------------------
__global__ __launch_bounds__(256)
void copy_wv_kernel(const float* __restrict__ Wv)
{
    int row = blockIdx.x;
    int tid = threadIdx.x;
    float4 v = *(const float4*)(Wv + (size_t)row * 1024 + tid * 4);
    __half* dst = g_WBIGH + (size_t)(2048 + row) * 1024 + tid * 4;
    *(half2*)(dst)     = __floats2half2_rn(v.x, v.y);
    *(half2*)(dst + 2) = __floats2half2_rn(v.z, v.w);
}

// ------------------------- round fp32 -> fp16 --------------------------------
__global__ __launch_bounds__(256)
void round_half_kernel(const float* __restrict__ src, __half* __restrict__ dst)
{
    size_t i = ((size_t)blockIdx.x * 256 + threadIdx.x) * 4;
    float4 v = *(const float4*)(src + i);
    *(half2*)(dst + i)     = __floats2half2_rn(v.x, v.y);
    *(half2*)(dst + i + 2) = __floats2half2_rn(v.z, v.w);
}

// ------------------------- fp16 mma GEMM (R7 config) ------------------------
constexpr int HROW_B   = 80;
constexpr int H_TILE_B = 128 * HROW_B;             // 10240 B per A/B tile
constexpr int H_STAGE  = 2 * H_TILE_B;             // 20480
constexpr int H_STAGES = 4;
constexpr int GEMM_SMEM = H_STAGES * H_STAGE;      // 81920 B

template<typename OutT, bool RELU, bool BIAS>
__global__ __launch_bounds__(128, 2)
void gemm_mma(const __half* __restrict__ A, const __half* __restrict__ Bm,
              const float* __restrict__ bias, OutT* __restrict__ C,
              int M, int N, int K, int relu_cols)
{
    extern __shared__ char smem[];
    const int tid = threadIdx.x;
    const int m0 = blockIdx.y * 128;
    const int n0 = blockIdx.x * 128;
    const int KT = K >> 5;

    const uint32_t smem_base = smem_u32(smem);

    auto load_stage = [&](int kt, int buf) {
        uint32_t ab = smem_base + buf * H_STAGE;
        uint32_t bb = ab + H_TILE_B;
        const __half* Asrc = A + (size_t)m0 * K + kt * 32;
        const __half* Bsrc = Bm + (size_t)n0 * K + kt * 32;
#pragma unroll
        for (int j = 0; j < 4; j++) {
            int o = tid + j * 128;
            int r = o >> 2, cc = o & 3;
            cp16(ab + (uint32_t)(r * HROW_B + cc * 16),
                 Asrc + (size_t)r * K + cc * 8);
            cp16(bb + (uint32_t)(r * HROW_B + cc * 16),
                 Bsrc + (size_t)r * K + cc * 8);
        }
    };

    const int wid  = tid >> 5;
    const int lane = tid & 31;
    const int wm = wid & 1;
    const int wn = wid >> 1;
    const int g  = lane >> 2;
    const int tg = lane & 3;

    const uint32_t aoff = (uint32_t)((wm * 64 + (lane & 15)) * HROW_B
                                     + ((lane & 16) ? 16 : 0));
    const uint32_t boff = (uint32_t)((wn * 64 + ((lane & 16) ? 8 : 0)
                                      + (lane & 7)) * HROW_B
                                     + ((lane & 8) ? 16 : 0));

    float acc[4][8][4];
#pragma unroll
    for (int mi = 0; mi < 4; mi++)
#pragma unroll
        for (int ni = 0; ni < 8; ni++)
#pragma unroll
            for (int q = 0; q < 4; q++) acc[mi][ni][q] = 0.f;

    load_stage(0, 0);
    asm volatile("cp.async.commit_group;" ::: "memory");
    load_stage(1, 1);
    asm volatile("cp.async.commit_group;" ::: "memory");
    load_stage(2, 2);
    asm volatile("cp.async.commit_group;" ::: "memory");

    for (int kt = 0; kt < KT; kt++) {
        asm volatile("cp.async.wait_group 2;" ::: "memory");
        __syncthreads();

        if (kt + 3 < KT) load_stage(kt + 3, (kt + 3) & 3);
        asm volatile("cp.async.commit_group;" ::: "memory");

        uint32_t As = smem_base + (kt & 3) * H_STAGE;
        uint32_t Bs = As + H_TILE_B;

#pragma unroll
        for (int ks = 0; ks < 2; ks++) {
            uint32_t kofs = ks * 32;
            uint32_t af[4][4];
#pragma unroll
            for (int mi = 0; mi < 4; mi++)
                ldsm_x4(af[mi][0], af[mi][1], af[mi][2], af[mi][3],
                        As + aoff + mi * (16 * HROW_B) + kofs);
            uint32_t bf[8][2];
#pragma unroll
            for (int nj = 0; nj < 4; nj++)
                ldsm_x4(bf[nj * 2][0], bf[nj * 2][1],
                        bf[nj * 2 + 1][0], bf[nj * 2 + 1][1],
                        Bs + boff + nj * (16 * HROW_B) + kofs);
#pragma unroll
            for (int mi = 0; mi < 4; mi++)
#pragma unroll
                for (int ni = 0; ni < 8; ni++)
                    mma_f16(acc[mi][ni], af[mi][0], af[mi][1], af[mi][2],
                            af[mi][3], bf[ni][0], bf[ni][1]);
        }
    }

#pragma unroll
    for (int mi = 0; mi < 4; mi++) {
        int row0 = m0 + wm * 64 + mi * 16 + g;
#pragma unroll
        for (int ni = 0; ni < 8; ni++) {
            int col = n0 + wn * 64 + ni * 8 + tg * 2;
            float2 v0 = make_float2(acc[mi][ni][0], acc[mi][ni][1]);
            float2 v1 = make_float2(acc[mi][ni][2], acc[mi][ni][3]);
            if (BIAS) {
                float2 b2 = *(const float2*)(bias + col);
                v0.x += b2.x; v0.y += b2.y;
                v1.x += b2.x; v1.y += b2.y;
            }
            if (RELU && col < relu_cols) {
                v0.x = fmaxf(v0.x, 0.f); v0.y = fmaxf(v0.y, 0.f);
                v1.x = fmaxf(v1.x, 0.f); v1.y = fmaxf(v1.y, 0.f);
            }
            if constexpr (sizeof(OutT) == 2) {
                *(half2*)((__half*)C + (size_t)row0 * N + col) =
                    __floats2half2_rn(v0.x, v0.y);
                *(half2*)((__half*)C + (size_t)(row0 + 8) * N + col) =
                    __floats2half2_rn(v1.x, v1.y);
            } else {
                *(float2*)((float*)C + (size_t)row0 * N + col) = v0;
                *(float2*)((float*)C + (size_t)(row0 + 8) * N + col) = v1;
            }
        }
    }
}

// ------------------------- K4: kv + ksum via tensor cores --------------------
// kv[d][e] = sum_n phiK[n][d] * V[n][e]  per (b,h); split-K over 8 splits.
// Both operands live as rows [n][64] in PHIVH -> transposed via ldmatrix.trans.
// 128 threads = 4 warps; warp w owns d rows [16w,16w+16), all 64 e.
// 64-row chunks staged via cp.async (3 buffers). 144B row stride: the 8 rows
// of each ldmatrix hit 8 distinct 16B banks columns (9n mod 8 = n mod 8).
constexpr int KVROW_B   = 144;
constexpr int KV_TILE_B = 64 * KVROW_B;            // 9216
constexpr int KV_STAGE  = 2 * KV_TILE_B;           // 18432 (PK + VV)
constexpr int KV_SMEM   = 3 * KV_STAGE;            // 55296

__global__ __launch_bounds__(128)
void kv_mma_kernel()
{
    extern __shared__ char skv[];
    const uint32_t sb = smem_u32(skv);
    const int tid = threadIdx.x;
    const int wid = tid >> 5;
    const int lane = tid & 31;
    const int split = blockIdx.x;
    const int bh = blockIdx.y;
    const int b = bh >> 4, h = bh & 15;
    const size_t base_row = (size_t)b * 4096 + split * 512;
    const __half* PKg = g_PHIVH + 1024 + h * 64;   // phiK slice base
    const __half* VVg = g_PHIVH + 2048 + h * 64;   // V slice base

    auto load_chunk = [&](int c, int buf) {
        uint32_t pb = sb + buf * KV_STAGE;
        uint32_t vb = pb + KV_TILE_B;
        size_t row0 = base_row + c * 64;
#pragma unroll
        for (int j = 0; j < 4; j++) {              // 512 cp16 per tile / 128
            int o = tid + j * 128;
            int r = o >> 3, cc = o & 7;
            size_t off = (row0 + r) * 3072 + cc * 8;
            cp16(pb + (uint32_t)(r * KVROW_B + cc * 16), PKg + off);
            cp16(vb + (uint32_t)(r * KVROW_B + cc * 16), VVg + off);
        }
    };

    // ldmatrix.trans lane->source-row mapping
    // A quadrants (d,n): r0=(d0:8,n0:8) r1=(d8:16,n0:8) r2=(d0:8,n8:16) r3=(d8,n8)
    const uint32_t a_off = (uint32_t)((((lane & 16) ? 8 : 0) + (lane & 7)) * KVROW_B
                                      + wid * 32 + ((lane & 8) ? 16 : 0));
    // B quadrants (k=n, n=e): r0=b0(e0:8) r1=b1(e0:8) r2=b0(e8:16) r3=b1(e8:16)
    const uint32_t b_off = (uint32_t)((((lane & 8) ? 8 : 0) + (lane & 7)) * KVROW_B
                                      + ((lane & 16) ? 16 : 0));

    float acc[8][4];
#pragma unroll
    for (int ni = 0; ni < 8; ni++)
#pragma unroll
        for (int q = 0; q < 4; q++) acc[ni][q] = 0.f;
    float ks = 0.f;

    load_chunk(0, 0);
    asm volatile("cp.async.commit_group;" ::: "memory");
    load_chunk(1, 1);
    asm volatile("cp.async.commit_group;" ::: "memory");

    for (int c = 0; c < 8; c++) {
        asm volatile("cp.async.wait_group 1;" ::: "memory");
        __syncthreads();
        if (c + 2 < 8) load_chunk(c + 2, (c + 2) % 3);
        asm volatile("cp.async.commit_group;" ::: "memory");

        uint32_t pb = sb + (c % 3) * KV_STAGE;
        uint32_t vb = pb + KV_TILE_B;

        // ksum over this chunk (threads 0-63, one d each)
        if (tid < 64) {
            const __half* pk = (const __half*)(skv + (c % 3) * KV_STAGE);
#pragma unroll 8
            for (int n = 0; n < 64; n++)
                ks += __half2float(*(const __half*)((const char*)pk
                                                    + n * KVROW_B + tid * 2));
        }

#pragma unroll
        for (int kk = 0; kk < 4; kk++) {
            uint32_t a0, a1, a2, a3;
            ldsm_x4_t(a0, a1, a2, a3, pb + kk * (16 * KVROW_B) + a_off);
#pragma unroll
            for (int eb = 0; eb < 4; eb++) {
                uint32_t r0, r1, r2, r3;
                ldsm_x4_t(r0, r1, r2, r3,
                          vb + kk * (16 * KVROW_B) + b_off + eb * 32);
                mma_f16(acc[eb * 2],     a0, a1, a2, a3, r0, r1);
                mma_f16(acc[eb * 2 + 1], a0, a1, a2, a3, r2, r3);
            }
        }
    }

    float* dst = g_KVP + (size_t)(split * 64 + bh) * 4096;
    int g = lane >> 2, tg = lane & 3;
#pragma unroll
    for (int ni = 0; ni < 8; ni++) {
        int e = ni * 8 + tg * 2;
        int d0 = wid * 16 + g;
        dst[d0 * 64 + e]           = acc[ni][0];
        dst[d0 * 64 + e + 1]       = acc[ni][1];
        dst[(d0 + 8) * 64 + e]     = acc[ni][2];
        dst[(d0 + 8) * 64 + e + 1] = acc[ni][3];
    }
    if (tid < 64) g_KSP[(split * 64 + bh) * 64 + tid] = ks;
}

// ------------------------- K5: deterministic reduction ----------------------
__global__ __launch_bounds__(256)
void kv_reduce_kernel()
{
    int idx = blockIdx.x * 256 + threadIdx.x;
    if (idx < 64 * 4096) {
        int bh = idx >> 12, r = idx & 4095;
        float s = 0.f;
#pragma unroll
        for (int sp = 0; sp < 8; sp++)
            s += g_KVP[(size_t)(sp * 64 + bh) * 4096 + r];
        g_KV[idx] = s;
    } else {
        int j = idx - 64 * 4096;
        if (j < 64 * 64) {
            int bh = j >> 6, d = j & 63;
            float s = 0.f;
#pragma unroll
            for (int sp = 0; sp < 8; sp++)
                s += g_KSP[(sp * 64 + bh) * 64 + d];
            g_KSUM[j] = s;
        }
    }
}

// ------------------------- K6: attn = inv * phiQ @ kv (fp16 out) ------------
__global__ __launch_bounds__(256)
void attn_kernel()
{
    int chunkb = blockIdx.x;
    int bh = blockIdx.y;
    int b = bh >> 4, h = bh & 15;
    __shared__ float KVs[64][64];
    __shared__ float KSs[64];
    int tid = threadIdx.x;
#pragma unroll
    for (int i = 0; i < 4; i++) {
        int f = tid + i * 256;
        *(float4*)&KVs[f >> 4][(f & 15) << 2] =
            *(const float4*)(g_KV + (size_t)bh * 4096 + f * 4);
    }
    if (tid < 64) KSs[tid] = g_KSUM[bh * 64 + tid];
    __syncthreads();

    int r = tid >> 1, halfsel = tid & 1;
    size_t m = (size_t)b * 4096 + chunkb * 128 + r;
    const __half* phq = g_PHIVH + m * 3072 + h * 64;

    float acc[32];
#pragma unroll
    for (int j = 0; j < 32; j++) acc[j] = 0.f;
    float denom = 0.f;

#pragma unroll
    for (int d0 = 0; d0 < 64; d0 += 16) {
        float q[16];
#pragma unroll
        for (int i = 0; i < 8; i++) {
            float2 t = __half22float2(*(const half2*)(phq + d0 + i * 2));
            q[i * 2] = t.x; q[i * 2 + 1] = t.y;
        }
#pragma unroll
        for (int dd = 0; dd < 16; dd++) {
            int d = d0 + dd;
            float p = q[dd];
            denom += p * KSs[d];
#pragma unroll
            for (int j = 0; j < 32; j += 4) {
                float4 kvv = *(float4*)&KVs[d][halfsel * 32 + j];
                acc[j]     += p * kvv.x;
                acc[j + 1] += p * kvv.y;
                acc[j + 2] += p * kvv.z;
                acc[j + 3] += p * kvv.w;
            }
        }
    }
    float inv = 1.0f / (0.125f * denom + 1e-8f);
    __half* dst = g_ATTNH + m * 1024 + h * 64 + halfsel * 32;
#pragma unroll
    for (int j = 0; j < 32; j += 2)
        *(half2*)(dst + j) = __floats2half2_rn(acc[j] * inv, acc[j + 1] * inv);
}

// ------------------------- launch -------------------------------------------
extern "C" void kernel_launch(void* const* d_in, const int* in_sizes, int n_in,
                              void* d_out, int out_size)
{
    const float* query = (const float*)d_in[0];
    const float* Wq    = (const float*)d_in[1];
    const float* Wk    = (const float*)d_in[2];
    const float* Wv    = (const float*)d_in[3];
    const float* P     = (const float*)d_in[4];
    const float* Wo    = (const float*)d_in[5];
    const float* bo    = (const float*)d_in[6];
    float* out = (float*)d_out;

    void *p_xh, *p_wbigh, *p_worh, *p_attnh, *p_phivh;
    cudaGetSymbolAddress(&p_xh,     g_XH);
    cudaGetSymbolAddress(&p_wbigh,  g_WBIGH);
    cudaGetSymbolAddress(&p_worh,   g_WORH);
    cudaGetSymbolAddress(&p_attnh,  g_ATTNH);
    cudaGetSymbolAddress(&p_phivh,  g_PHIVH);

    cudaFuncSetAttribute((const void*)gemm_mma<__half, true, false>,
                         cudaFuncAttributeMaxDynamicSharedMemorySize, GEMM_SMEM);
    cudaFuncSetAttribute((const void*)gemm_mma<float, false, true>,
                         cudaFuncAttributeMaxDynamicSharedMemorySize, GEMM_SMEM);
    cudaFuncSetAttribute((const void*)kv_mma_kernel,
                         cudaFuncAttributeMaxDynamicSharedMemorySize, KV_SMEM);

    build_weff_kernel<<<512, 256>>>(Wq, Wk, P);
    copy_wv_kernel<<<1024, 256>>>(Wv);
    round_half_kernel<<<16384, 256>>>(query, (__half*)p_xh);
    round_half_kernel<<<1024, 256>>>(Wo, (__half*)p_worh);

    // PHIVH = relu(XH @ WBIGH^T) on first 2048 cols (fp16 out)
    gemm_mma<__half, true, false><<<dim3(24, 128), 128, GEMM_SMEM>>>(
        (const __half*)p_xh, (const __half*)p_wbigh, nullptr,
        (__half*)p_phivh, 16384, 3072, 1024, 2048);

    kv_mma_kernel<<<dim3(8, 64), 128, KV_SMEM>>>();
    kv_reduce_kernel<<<1040, 256>>>();
    attn_kernel<<<dim3(32, 64), 256>>>();   // writes fp16 ATTN

    // out = ATTNH @ WORH^T + bo (fp32 out)
    gemm_mma<float, false, true><<<dim3(8, 128), 128, GEMM_SMEM>>>(
        (const __half*)p_attnh, (const __half*)p_worh, bo, out,
        16384, 1024, 1024, 0);
}

// round 9
// speedup vs baseline: 1.5959x; 1.1840x over previous
#include <cuda_runtime.h>
#include <cuda_fp16.h>
#include <cstdint>

// ---------------------------------------------------------------------------
// FastAttention — linear attention with ReLU feature maps.
// Big GEMMs: fp16 mma m16n8k16, CTA 128x128x64, 128 thr (warp 64x64),
// 3-stage cp.async (144B rows), 1 sync/iter, 2 CTAs/SM.
// kv and attn both on tensor cores. PHIV fp16. fp32 accumulation.
// ---------------------------------------------------------------------------

// ------------------------- device scratch (no allocs) ----------------------
__device__ __align__(16) __half g_XH[(size_t)16384 * 1024];
__device__ __align__(16) __half g_WBIGH[(size_t)3072 * 1024];
__device__ __align__(16) __half g_WORH[(size_t)1024 * 1024];
__device__ __align__(16) __half g_ATTNH[(size_t)16384 * 1024];
__device__ __align__(16) __half g_PHIVH[(size_t)16384 * 3072];
__device__ __align__(16) __half g_KVHT[64 * 64 * 64];   // [bh][e][d] fp16
__device__ float g_KSUM[64 * 64];
__device__ float g_KVP[8 * 64 * 64 * 64];
__device__ float g_KSP[8 * 64 * 64];

// ------------------------- helpers ------------------------------------------
__device__ __forceinline__ uint32_t smem_u32(const void* p) {
    uint32_t a;
    asm("{ .reg .u64 t; cvta.to.shared.u64 t, %1; cvt.u32.u64 %0, t; }"
        : "=r"(a) : "l"(p));
    return a;
}
__device__ __forceinline__ void cp16(uint32_t dst, const void* src) {
    asm volatile("cp.async.cg.shared.global [%0], [%1], 16;" :: "r"(dst), "l"(src));
}
__device__ __forceinline__ void ldsm_x4(uint32_t& r0, uint32_t& r1,
                                        uint32_t& r2, uint32_t& r3, uint32_t a) {
    asm volatile("ldmatrix.sync.aligned.m8n8.x4.shared.b16 {%0,%1,%2,%3}, [%4];"
                 : "=r"(r0), "=r"(r1), "=r"(r2), "=r"(r3) : "r"(a));
}
__device__ __forceinline__ void ldsm_x4_t(uint32_t& r0, uint32_t& r1,
                                          uint32_t& r2, uint32_t& r3, uint32_t a) {
    asm volatile("ldmatrix.sync.aligned.m8n8.x4.trans.shared.b16 {%0,%1,%2,%3}, [%4];"
                 : "=r"(r0), "=r"(r1), "=r"(r2), "=r"(r3) : "r"(a));
}
__device__ __forceinline__ void mma_f16(float* c, uint32_t a0, uint32_t a1,
                                        uint32_t a2, uint32_t a3,
                                        uint32_t b0, uint32_t b1) {
    asm volatile(
        "mma.sync.aligned.m16n8k16.row.col.f32.f16.f16.f32 "
        "{%0,%1,%2,%3}, {%4,%5,%6,%7}, {%8,%9}, {%0,%1,%2,%3};"
        : "+f"(c[0]), "+f"(c[1]), "+f"(c[2]), "+f"(c[3])
        : "r"(a0), "r"(a1), "r"(a2), "r"(a3), "r"(b0), "r"(b1));
}

// ------------------------- K1: fused per-head weights (fp16 out) ------------
__global__ __launch_bounds__(256)
void build_weff_kernel(const float* __restrict__ Wq,
                       const float* __restrict__ Wk,
                       const float* __restrict__ P)
{
    int bid   = blockIdx.x;
    int which = bid >> 8;
    int rem   = bid & 255;
    int h     = rem >> 4;
    int chunk = rem & 15;
    const float* W = which ? Wk : Wq;

    __shared__ float Psh[64][64];
    __shared__ float Wsh[64][64];
    int tid = threadIdx.x;

#pragma unroll
    for (int i = 0; i < 4; i++) {
        int f = tid + i * 256;
        int e = f >> 4, c4 = (f & 15) << 2;
        *(float4*)&Psh[e][c4] = *(const float4*)(P + (size_t)h * 4096 + f * 4);
        *(float4*)&Wsh[e][c4] =
            *(const float4*)(W + (size_t)(h * 64 + e) * 1024 + chunk * 64 + c4);
    }
    __syncthreads();

    int dp = tid & 63;
    int dg = tid >> 6;
    float acc[16];
#pragma unroll
    for (int j = 0; j < 16; j++) acc[j] = 0.f;
#pragma unroll 4
    for (int e = 0; e < 64; e++) {
        float p = Psh[e][dp];
#pragma unroll
        for (int j = 0; j < 16; j++)
            acc[j] += p * Wsh[e][dg * 16 + j];
    }
    __half* dst = g_WBIGH + (size_t)(which * 1024 + h * 64 + dp) * 1024
                          + chunk * 64 + dg * 16;
#pragma unroll
    for (int j = 0; j < 16; j += 2)
        *(half2*)(dst + j) = __floats2half2_rn(acc[j], acc[j + 1]);
}

// ------------------------- K2: copy Wv (fp16) --------------------------------
__global__ __launch_bounds__(256)
void copy_wv_kernel(const float* __restrict__ Wv)
{
    int row = blockIdx.x;
    int tid = threadIdx.x;
    float4 v = *(const float4*)(Wv + (size_t)row * 1024 + tid * 4);
    __half* dst = g_WBIGH + (size_t)(2048 + row) * 1024 + tid * 4;
    *(half2*)(dst)     = __floats2half2_rn(v.x, v.y);
    *(half2*)(dst + 2) = __floats2half2_rn(v.z, v.w);
}

// ------------------------- round fp32 -> fp16 --------------------------------
__global__ __launch_bounds__(256)
void round_half_kernel(const float* __restrict__ src, __half* __restrict__ dst)
{
    size_t i = ((size_t)blockIdx.x * 256 + threadIdx.x) * 4;
    float4 v = *(const float4*)(src + i);
    *(half2*)(dst + i)     = __floats2half2_rn(v.x, v.y);
    *(half2*)(dst + i + 2) = __floats2half2_rn(v.z, v.w);
}

// ------------------------- fp16 mma GEMM (k-chunk 64) -----------------------
// CTA tile 128x128x64, 128 threads (4 warps 2x2), warp tile 64x64.
// 3-stage cp.async ring, 144B padded rows, single sync per k-iteration.
constexpr int HROW_B   = 144;                      // 128B data + 16B pad
constexpr int H_TILE_B = 128 * HROW_B;             // 18432 per A/B tile
constexpr int H_STAGE  = 2 * H_TILE_B;             // 36864
constexpr int H_STAGES = 3;
constexpr int GEMM_SMEM = H_STAGES * H_STAGE;      // 110592 B

template<typename OutT, bool RELU, bool BIAS>
__global__ __launch_bounds__(128, 2)
void gemm_mma(const __half* __restrict__ A, const __half* __restrict__ Bm,
              const float* __restrict__ bias, OutT* __restrict__ C,
              int M, int N, int K, int relu_cols)
{
    extern __shared__ char smem[];
    const int tid = threadIdx.x;
    const int m0 = blockIdx.y * 128;
    const int n0 = blockIdx.x * 128;
    const int KT = K >> 6;                         // chunks of 64 halfs

    const uint32_t smem_base = smem_u32(smem);

    auto load_stage = [&](int kt, int buf) {
        uint32_t ab = smem_base + buf * H_STAGE;
        uint32_t bb = ab + H_TILE_B;
        const __half* Asrc = A + (size_t)m0 * K + kt * 64;
        const __half* Bsrc = Bm + (size_t)n0 * K + kt * 64;
#pragma unroll
        for (int j = 0; j < 8; j++) {              // 1024 cp16 per tile
            int o = tid + j * 128;
            int r = o >> 3, cc = o & 7;
            cp16(ab + (uint32_t)(r * HROW_B + cc * 16),
                 Asrc + (size_t)r * K + cc * 8);
            cp16(bb + (uint32_t)(r * HROW_B + cc * 16),
                 Bsrc + (size_t)r * K + cc * 8);
        }
    };

    const int wid  = tid >> 5;
    const int lane = tid & 31;
    const int wm = wid & 1;
    const int wn = wid >> 1;
    const int g  = lane >> 2;
    const int tg = lane & 3;

    const uint32_t aoff = (uint32_t)((wm * 64 + (lane & 15)) * HROW_B
                                     + ((lane & 16) ? 16 : 0));
    const uint32_t boff = (uint32_t)((wn * 64 + ((lane & 16) ? 8 : 0)
                                      + (lane & 7)) * HROW_B
                                     + ((lane & 8) ? 16 : 0));

    float acc[4][8][4];
#pragma unroll
    for (int mi = 0; mi < 4; mi++)
#pragma unroll
        for (int ni = 0; ni < 8; ni++)
#pragma unroll
            for (int q = 0; q < 4; q++) acc[mi][ni][q] = 0.f;

    load_stage(0, 0);
    asm volatile("cp.async.commit_group;" ::: "memory");
    load_stage(1, 1);
    asm volatile("cp.async.commit_group;" ::: "memory");

    for (int kt = 0; kt < KT; kt++) {
        asm volatile("cp.async.wait_group 1;" ::: "memory");
        // publishes stage kt arrivals; frees stage (kt+2)%3 (read at kt-1)
        __syncthreads();

        if (kt + 2 < KT) load_stage(kt + 2, (kt + 2) % 3);
        asm volatile("cp.async.commit_group;" ::: "memory");

        uint32_t As = smem_base + (kt % 3) * H_STAGE;
        uint32_t Bs = As + H_TILE_B;

#pragma unroll
        for (int ks = 0; ks < 4; ks++) {
            uint32_t kofs = ks * 32;               // 16 halfs = 32 B
            uint32_t af[4][4];
#pragma unroll
            for (int mi = 0; mi < 4; mi++)
                ldsm_x4(af[mi][0], af[mi][1], af[mi][2], af[mi][3],
                        As + aoff + mi * (16 * HROW_B) + kofs);
            uint32_t bf[8][2];
#pragma unroll
            for (int nj = 0; nj < 4; nj++)
                ldsm_x4(bf[nj * 2][0], bf[nj * 2][1],
                        bf[nj * 2 + 1][0], bf[nj * 2 + 1][1],
                        Bs + boff + nj * (16 * HROW_B) + kofs);
#pragma unroll
            for (int mi = 0; mi < 4; mi++)
#pragma unroll
                for (int ni = 0; ni < 8; ni++)
                    mma_f16(acc[mi][ni], af[mi][0], af[mi][1], af[mi][2],
                            af[mi][3], bf[ni][0], bf[ni][1]);
        }
    }

#pragma unroll
    for (int mi = 0; mi < 4; mi++) {
        int row0 = m0 + wm * 64 + mi * 16 + g;
#pragma unroll
        for (int ni = 0; ni < 8; ni++) {
            int col = n0 + wn * 64 + ni * 8 + tg * 2;
            float2 v0 = make_float2(acc[mi][ni][0], acc[mi][ni][1]);
            float2 v1 = make_float2(acc[mi][ni][2], acc[mi][ni][3]);
            if (BIAS) {
                float2 b2 = *(const float2*)(bias + col);
                v0.x += b2.x; v0.y += b2.y;
                v1.x += b2.x; v1.y += b2.y;
            }
            if (RELU && col < relu_cols) {
                v0.x = fmaxf(v0.x, 0.f); v0.y = fmaxf(v0.y, 0.f);
                v1.x = fmaxf(v1.x, 0.f); v1.y = fmaxf(v1.y, 0.f);
            }
            if constexpr (sizeof(OutT) == 2) {
                *(half2*)((__half*)C + (size_t)row0 * N + col) =
                    __floats2half2_rn(v0.x, v0.y);
                *(half2*)((__half*)C + (size_t)(row0 + 8) * N + col) =
                    __floats2half2_rn(v1.x, v1.y);
            } else {
                *(float2*)((float*)C + (size_t)row0 * N + col) = v0;
                *(float2*)((float*)C + (size_t)(row0 + 8) * N + col) = v1;
            }
        }
    }
}

// ------------------------- K4: kv + ksum via tensor cores --------------------
constexpr int KVROW_B   = 144;
constexpr int KV_TILE_B = 64 * KVROW_B;            // 9216
constexpr int KV_STAGE  = 2 * KV_TILE_B;           // 18432
constexpr int KV_SMEM   = 3 * KV_STAGE;            // 55296

__global__ __launch_bounds__(128)
void kv_mma_kernel()
{
    extern __shared__ char skv[];
    const uint32_t sb = smem_u32(skv);
    const int tid = threadIdx.x;
    const int wid = tid >> 5;
    const int lane = tid & 31;
    const int split = blockIdx.x;
    const int bh = blockIdx.y;
    const int b = bh >> 4, h = bh & 15;
    const size_t base_row = (size_t)b * 4096 + split * 512;
    const __half* PKg = g_PHIVH + 1024 + h * 64;
    const __half* VVg = g_PHIVH + 2048 + h * 64;

    auto load_chunk = [&](int c, int buf) {
        uint32_t pb = sb + buf * KV_STAGE;
        uint32_t vb = pb + KV_TILE_B;
        size_t row0 = base_row + c * 64;
#pragma unroll
        for (int j = 0; j < 4; j++) {
            int o = tid + j * 128;
            int r = o >> 3, cc = o & 7;
            size_t off = (row0 + r) * 3072 + cc * 8;
            cp16(pb + (uint32_t)(r * KVROW_B + cc * 16), PKg + off);
            cp16(vb + (uint32_t)(r * KVROW_B + cc * 16), VVg + off);
        }
    };

    const uint32_t a_off = (uint32_t)((((lane & 16) ? 8 : 0) + (lane & 7)) * KVROW_B
                                      + wid * 32 + ((lane & 8) ? 16 : 0));
    const uint32_t b_off = (uint32_t)((((lane & 8) ? 8 : 0) + (lane & 7)) * KVROW_B
                                      + ((lane & 16) ? 16 : 0));

    float acc[8][4];
#pragma unroll
    for (int ni = 0; ni < 8; ni++)
#pragma unroll
        for (int q = 0; q < 4; q++) acc[ni][q] = 0.f;
    float ks = 0.f;

    load_chunk(0, 0);
    asm volatile("cp.async.commit_group;" ::: "memory");
    load_chunk(1, 1);
    asm volatile("cp.async.commit_group;" ::: "memory");

    for (int c = 0; c < 8; c++) {
        asm volatile("cp.async.wait_group 1;" ::: "memory");
        __syncthreads();
        if (c + 2 < 8) load_chunk(c + 2, (c + 2) % 3);
        asm volatile("cp.async.commit_group;" ::: "memory");

        uint32_t pb = sb + (c % 3) * KV_STAGE;
        uint32_t vb = pb + KV_TILE_B;

        if (tid < 64) {
            const __half* pk = (const __half*)(skv + (c % 3) * KV_STAGE);
#pragma unroll 8
            for (int n = 0; n < 64; n++)
                ks += __half2float(*(const __half*)((const char*)pk
                                                    + n * KVROW_B + tid * 2));
        }

#pragma unroll
        for (int kk = 0; kk < 4; kk++) {
            uint32_t a0, a1, a2, a3;
            ldsm_x4_t(a0, a1, a2, a3, pb + kk * (16 * KVROW_B) + a_off);
#pragma unroll
            for (int eb = 0; eb < 4; eb++) {
                uint32_t r0, r1, r2, r3;
                ldsm_x4_t(r0, r1, r2, r3,
                          vb + kk * (16 * KVROW_B) + b_off + eb * 32);
                mma_f16(acc[eb * 2],     a0, a1, a2, a3, r0, r1);
                mma_f16(acc[eb * 2 + 1], a0, a1, a2, a3, r2, r3);
            }
        }
    }

    float* dst = g_KVP + (size_t)(split * 64 + bh) * 4096;
    int g = lane >> 2, tg = lane & 3;
#pragma unroll
    for (int ni = 0; ni < 8; ni++) {
        int e = ni * 8 + tg * 2;
        int d0 = wid * 16 + g;
        dst[d0 * 64 + e]           = acc[ni][0];
        dst[d0 * 64 + e + 1]       = acc[ni][1];
        dst[(d0 + 8) * 64 + e]     = acc[ni][2];
        dst[(d0 + 8) * 64 + e + 1] = acc[ni][3];
    }
    if (tid < 64) g_KSP[(split * 64 + bh) * 64 + tid] = ks;
}

// ------------------------- K5: reduction -> fp16 transposed kv ---------------
__global__ __launch_bounds__(256)
void kv_reduce_kernel()
{
    int idx = blockIdx.x * 256 + threadIdx.x;
    if (idx < 64 * 4096) {
        int bh = idx >> 12, r = idx & 4095;
        float s = 0.f;
#pragma unroll
        for (int sp = 0; sp < 8; sp++)
            s += g_KVP[(size_t)(sp * 64 + bh) * 4096 + r];
        int d = r >> 6, e = r & 63;
        g_KVHT[(bh << 12) + (e << 6) + d] = __float2half(s);
    } else {
        int j = idx - 64 * 4096;
        if (j < 64 * 64) {
            int bh = j >> 6, d = j & 63;
            float s = 0.f;
#pragma unroll
            for (int sp = 0; sp < 8; sp++)
                s += g_KSP[(sp * 64 + bh) * 64 + d];
            g_KSUM[j] = s;
        }
    }
}

// ------------------------- K6: attn via tensor cores -------------------------
// attn[n,e] = inv[n] * sum_d phiQ[n,d] * kv[d,e];  kv^T fp16 in g_KVHT.
// 128 threads (4 warps), block = 128 token rows of one (b,h).
__global__ __launch_bounds__(128)
void attn_mma_kernel()
{
    __shared__ __align__(16) char sPQ[128 * 144];
    __shared__ __align__(16) char sKV[64 * 144];
    __shared__ float sDen[128];
    __shared__ float sKS[64];

    const int tid = threadIdx.x;
    const int wid = tid >> 5;
    const int lane = tid & 31;
    const int chunk = blockIdx.x;
    const int bh = blockIdx.y;
    const int b = bh >> 4, h = bh & 15;
    const size_t m0 = (size_t)b * 4096 + chunk * 128;

    const uint32_t pqb = smem_u32(sPQ);
    const uint32_t kvb = smem_u32(sKV);

    const __half* PQg = g_PHIVH + h * 64;
#pragma unroll
    for (int j = 0; j < 8; j++) {                  // 1024 cp16
        int o = tid + j * 128;
        int r = o >> 3, cc = o & 7;
        cp16(pqb + (uint32_t)(r * 144 + cc * 16), PQg + (m0 + r) * 3072 + cc * 8);
    }
    const __half* KVg = g_KVHT + ((size_t)bh << 12);
#pragma unroll
    for (int j = 0; j < 4; j++) {                  // 512 cp16
        int o = tid + j * 128;
        int r = o >> 3, cc = o & 7;
        cp16(kvb + (uint32_t)(r * 144 + cc * 16), KVg + r * 64 + cc * 8);
    }
    asm volatile("cp.async.commit_group;" ::: "memory");
    if (tid < 64) sKS[tid] = g_KSUM[bh * 64 + tid];
    asm volatile("cp.async.wait_group 0;" ::: "memory");
    __syncthreads();

    // per-row denominator (thread tid -> row tid)
    {
        const __half* pq = (const __half*)(sPQ + tid * 144);
        float den = 0.f;
#pragma unroll 16
        for (int d = 0; d < 64; d++)
            den += __half2float(pq[d]) * sKS[d];
        sDen[tid] = 1.0f / (0.125f * den + 1e-8f);
    }

    const uint32_t aoff = pqb + (uint32_t)((wid * 32 + (lane & 15)) * 144
                                           + ((lane & 16) ? 16 : 0));
    const uint32_t boff = kvb + (uint32_t)((((lane & 16) ? 8 : 0) + (lane & 7)) * 144
                                           + ((lane & 8) ? 16 : 0));

    float acc[2][8][4];
#pragma unroll
    for (int mi = 0; mi < 2; mi++)
#pragma unroll
        for (int ni = 0; ni < 8; ni++)
#pragma unroll
            for (int q = 0; q < 4; q++) acc[mi][ni][q] = 0.f;

#pragma unroll
    for (int ksb = 0; ksb < 4; ksb++) {
        uint32_t kofs = ksb * 32;
        uint32_t af[2][4];
#pragma unroll
        for (int mi = 0; mi < 2; mi++)
            ldsm_x4(af[mi][0], af[mi][1], af[mi][2], af[mi][3],
                    aoff + mi * (16 * 144) + kofs);
        uint32_t bf[8][2];
#pragma unroll
        for (int nj = 0; nj < 4; nj++)
            ldsm_x4(bf[nj * 2][0], bf[nj * 2][1],
                    bf[nj * 2 + 1][0], bf[nj * 2 + 1][1],
                    boff + nj * (16 * 144) + kofs);
#pragma unroll
        for (int mi = 0; mi < 2; mi++)
#pragma unroll
            for (int ni = 0; ni < 8; ni++)
                mma_f16(acc[mi][ni], af[mi][0], af[mi][1], af[mi][2],
                        af[mi][3], bf[ni][0], bf[ni][1]);
    }
    __syncthreads();                                // sDen visible to all

    const int g = lane >> 2, tg = lane & 3;
#pragma unroll
    for (int mi = 0; mi < 2; mi++) {
        int row = wid * 32 + mi * 16 + g;
        float inv0 = sDen[row], inv1 = sDen[row + 8];
        __half* dst0 = g_ATTNH + (m0 + row) * 1024 + h * 64;
#pragma unroll
        for (int ni = 0; ni < 8; ni++) {
            int e = ni * 8 + tg * 2;
            *(half2*)(dst0 + e) =
                __floats2half2_rn(acc[mi][ni][0] * inv0, acc[mi][ni][1] * inv0);
            *(half2*)(dst0 + 8 * 1024 + e) =
                __floats2half2_rn(acc[mi][ni][2] * inv1, acc[mi][ni][3] * inv1);
        }
    }
}

// ------------------------- launch -------------------------------------------
extern "C" void kernel_launch(void* const* d_in, const int* in_sizes, int n_in,
                              void* d_out, int out_size)
{
    const float* query = (const float*)d_in[0];
    const float* Wq    = (const float*)d_in[1];
    const float* Wk    = (const float*)d_in[2];
    const float* Wv    = (const float*)d_in[3];
    const float* P     = (const float*)d_in[4];
    const float* Wo    = (const float*)d_in[5];
    const float* bo    = (const float*)d_in[6];
    float* out = (float*)d_out;

    void *p_xh, *p_wbigh, *p_worh, *p_attnh, *p_phivh;
    cudaGetSymbolAddress(&p_xh,     g_XH);
    cudaGetSymbolAddress(&p_wbigh,  g_WBIGH);
    cudaGetSymbolAddress(&p_worh,   g_WORH);
    cudaGetSymbolAddress(&p_attnh,  g_ATTNH);
    cudaGetSymbolAddress(&p_phivh,  g_PHIVH);

    cudaFuncSetAttribute((const void*)gemm_mma<__half, true, false>,
                         cudaFuncAttributeMaxDynamicSharedMemorySize, GEMM_SMEM);
    cudaFuncSetAttribute((const void*)gemm_mma<float, false, true>,
                         cudaFuncAttributeMaxDynamicSharedMemorySize, GEMM_SMEM);
    cudaFuncSetAttribute((const void*)kv_mma_kernel,
                         cudaFuncAttributeMaxDynamicSharedMemorySize, KV_SMEM);

    build_weff_kernel<<<512, 256>>>(Wq, Wk, P);
    copy_wv_kernel<<<1024, 256>>>(Wv);
    round_half_kernel<<<16384, 256>>>(query, (__half*)p_xh);
    round_half_kernel<<<1024, 256>>>(Wo, (__half*)p_worh);

    // PHIVH = relu(XH @ WBIGH^T) on first 2048 cols (fp16 out)
    gemm_mma<__half, true, false><<<dim3(24, 128), 128, GEMM_SMEM>>>(
        (const __half*)p_xh, (const __half*)p_wbigh, nullptr,
        (__half*)p_phivh, 16384, 3072, 1024, 2048);

    kv_mma_kernel<<<dim3(8, 64), 128, KV_SMEM>>>();
    kv_reduce_kernel<<<1040, 256>>>();
    attn_mma_kernel<<<dim3(32, 64), 128>>>();   // writes fp16 ATTN

    // out = ATTNH @ WORH^T + bo (fp32 out)
    gemm_mma<float, false, true><<<dim3(8, 128), 128, GEMM_SMEM>>>(
        (const __half*)p_attnh, (const __half*)p_worh, bo, out,
        16384, 1024, 1024, 0);
}